// round 1
// baseline (speedup 1.0000x reference)
#include <cuda_runtime.h>
#include <cuda_bf16.h>
#include <math.h>

// Problem constants
#define B   16
#define C   512
#define NSP 1024      // h*w = 32*32
#define NH  4
#define DH  128
#define NG  8
#define QKV_C (3*C)   // 1536

// ---------------- scratch (static __device__, no allocs) ----------------
__device__ float g_xn [(size_t)B*C*NSP];            // 33.5 MB  normalized x [b][c][n]
__device__ float g_qkv[(size_t)B*QKV_C*NSP];        // 100.7 MB qkv [b][o][n]
__device__ float g_q  [(size_t)B*NH*NSP*DH];        // 33.5 MB  [bh][n][d]
__device__ float g_k  [(size_t)B*NH*NSP*DH];
__device__ float g_v  [(size_t)B*NH*NSP*DH];
__device__ float g_S  [(size_t)B*NH*NSP*NSP];       // 268 MB   logits/probs [bh][n][m]
__device__ float g_o  [(size_t)B*NH*NSP*DH];        // 33.5 MB  [bh][n][d]
__device__ float g_att[(size_t)B*C*NSP];            // 33.5 MB  [b][c][n]

// ---------------- GroupNorm ----------------
// grid = B*NG blocks, 256 threads. Each group: 64 channels * 1024 = 65536 elems.
__global__ __launch_bounds__(256) void gn_kernel(
    const float* __restrict__ x, const float* __restrict__ gamma,
    const float* __restrict__ beta, float* __restrict__ xn)
{
    const int CG = C / NG;              // 64
    const int GE = CG * NSP;            // 65536
    int bg = blockIdx.x;
    int b = bg / NG, g = bg % NG;
    const float* xp = x  + ((size_t)b*C + (size_t)g*CG) * NSP;
    float*       op = xn + ((size_t)b*C + (size_t)g*CG) * NSP;
    int t = threadIdx.x;

    float s = 0.f, s2 = 0.f;
    for (int i = t; i < GE; i += 256) {
        float v = xp[i];
        s += v; s2 += v * v;
    }
    __shared__ float rs[256], rs2[256];
    rs[t] = s; rs2[t] = s2;
    __syncthreads();
    for (int st = 128; st > 0; st >>= 1) {
        if (t < st) { rs[t] += rs[t+st]; rs2[t] += rs2[t+st]; }
        __syncthreads();
    }
    float mu  = rs[0] * (1.f / GE);
    float var = rs2[0] * (1.f / GE) - mu * mu;
    float inv = rsqrtf(var + 1e-5f);

    for (int i = t; i < GE; i += 256) {
        int c = g * CG + i / NSP;
        op[i] = (xp[i] - mu) * inv * gamma[c] + beta[c];
    }
}

// ---------------- GEMM NN: C[M,N] = alpha * A[M,K] @ B[K,N] (+bias)(+res) ----------------
// Tiles: 128x128x16, 256 threads, 8x8 microtile per thread. All dims assumed multiples.
#define MT 128
#define NT 128
#define KT 16

__global__ __launch_bounds__(256) void gemm_nn(
    const float* __restrict__ A, long long sA,
    const float* __restrict__ Bm, long long sB,
    float* __restrict__ Cm, long long sC,
    int M, int N, int K,
    const float* __restrict__ bias,
    const float* __restrict__ res, long long sR,
    float alpha)
{
    __shared__ float As[KT][MT];
    __shared__ float Bs[KT][NT];
    int bz = blockIdx.z;
    A  += (size_t)sA * bz;
    Bm += (size_t)sB * bz;
    Cm += (size_t)sC * bz;
    if (res) res += (size_t)sR * bz;

    int m0 = blockIdx.y * MT;
    int n0 = blockIdx.x * NT;
    int t  = threadIdx.x;
    int tr = t >> 4, tc = t & 15;

    float acc[8][8];
#pragma unroll
    for (int i = 0; i < 8; i++)
#pragma unroll
        for (int j = 0; j < 8; j++) acc[i][j] = 0.f;

    for (int k0 = 0; k0 < K; k0 += KT) {
        // A tile [MT][KT] -> As[k][m] (transposed store)
#pragma unroll
        for (int l = 0; l < 2; l++) {
            int idx = (t + l*256) * 4;
            int m = idx / KT;
            int kk = idx % KT;
            float4 va = *(const float4*)&A[(size_t)(m0+m)*K + k0 + kk];
            As[kk+0][m] = va.x; As[kk+1][m] = va.y;
            As[kk+2][m] = va.z; As[kk+3][m] = va.w;
        }
        // B tile [KT][NT] coalesced
#pragma unroll
        for (int l = 0; l < 2; l++) {
            int idx = (t + l*256) * 4;
            int kk = idx / NT;
            int n  = idx % NT;
            *(float4*)&Bs[kk][n] = *(const float4*)&Bm[(size_t)(k0+kk)*N + n0 + n];
        }
        __syncthreads();
#pragma unroll
        for (int kk = 0; kk < KT; kk++) {
            float a[8], bb[8];
            *(float4*)&a[0]  = *(float4*)&As[kk][tr*8];
            *(float4*)&a[4]  = *(float4*)&As[kk][tr*8+4];
            *(float4*)&bb[0] = *(float4*)&Bs[kk][tc*8];
            *(float4*)&bb[4] = *(float4*)&Bs[kk][tc*8+4];
#pragma unroll
            for (int i = 0; i < 8; i++)
#pragma unroll
                for (int j = 0; j < 8; j++)
                    acc[i][j] += a[i] * bb[j];
        }
        __syncthreads();
    }

#pragma unroll
    for (int i = 0; i < 8; i++) {
        int m = m0 + tr*8 + i;
        float bv = bias ? bias[m] : 0.f;
#pragma unroll
        for (int j = 0; j < 8; j += 4) {
            int n = n0 + tc*8 + j;
            float4 r = make_float4(0.f, 0.f, 0.f, 0.f);
            if (res) r = *(const float4*)&res[(size_t)m*N + n];
            float4 o;
            o.x = alpha*acc[i][j+0] + bv + r.x;
            o.y = alpha*acc[i][j+1] + bv + r.y;
            o.z = alpha*acc[i][j+2] + bv + r.z;
            o.w = alpha*acc[i][j+3] + bv + r.w;
            *(float4*)&Cm[(size_t)m*N + n] = o;
        }
    }
}

// ---------------- GEMM NT: C[M,N] = alpha * A[M,K] @ B[N,K]^T ----------------
__global__ __launch_bounds__(256) void gemm_nt(
    const float* __restrict__ A, long long sA,
    const float* __restrict__ Bm, long long sB,
    float* __restrict__ Cm, long long sC,
    int M, int N, int K, float alpha)
{
    __shared__ float As[KT][MT];
    __shared__ float Bs[KT][NT];
    int bz = blockIdx.z;
    A  += (size_t)sA * bz;
    Bm += (size_t)sB * bz;
    Cm += (size_t)sC * bz;

    int m0 = blockIdx.y * MT;
    int n0 = blockIdx.x * NT;
    int t  = threadIdx.x;
    int tr = t >> 4, tc = t & 15;

    float acc[8][8];
#pragma unroll
    for (int i = 0; i < 8; i++)
#pragma unroll
        for (int j = 0; j < 8; j++) acc[i][j] = 0.f;

    for (int k0 = 0; k0 < K; k0 += KT) {
#pragma unroll
        for (int l = 0; l < 2; l++) {
            int idx = (t + l*256) * 4;
            int m = idx / KT;
            int kk = idx % KT;
            float4 va = *(const float4*)&A[(size_t)(m0+m)*K + k0 + kk];
            As[kk+0][m] = va.x; As[kk+1][m] = va.y;
            As[kk+2][m] = va.z; As[kk+3][m] = va.w;
        }
#pragma unroll
        for (int l = 0; l < 2; l++) {
            int idx = (t + l*256) * 4;
            int n = idx / KT;
            int kk = idx % KT;
            float4 vb = *(const float4*)&Bm[(size_t)(n0+n)*K + k0 + kk];
            Bs[kk+0][n] = vb.x; Bs[kk+1][n] = vb.y;
            Bs[kk+2][n] = vb.z; Bs[kk+3][n] = vb.w;
        }
        __syncthreads();
#pragma unroll
        for (int kk = 0; kk < KT; kk++) {
            float a[8], bb[8];
            *(float4*)&a[0]  = *(float4*)&As[kk][tr*8];
            *(float4*)&a[4]  = *(float4*)&As[kk][tr*8+4];
            *(float4*)&bb[0] = *(float4*)&Bs[kk][tc*8];
            *(float4*)&bb[4] = *(float4*)&Bs[kk][tc*8+4];
#pragma unroll
            for (int i = 0; i < 8; i++)
#pragma unroll
                for (int j = 0; j < 8; j++)
                    acc[i][j] += a[i] * bb[j];
        }
        __syncthreads();
    }

#pragma unroll
    for (int i = 0; i < 8; i++) {
        int m = m0 + tr*8 + i;
#pragma unroll
        for (int j = 0; j < 8; j += 4) {
            int n = n0 + tc*8 + j;
            float4 o;
            o.x = alpha*acc[i][j+0];
            o.y = alpha*acc[i][j+1];
            o.z = alpha*acc[i][j+2];
            o.w = alpha*acc[i][j+3];
            *(float4*)&Cm[(size_t)m*N + n] = o;
        }
    }
}

// ---------------- transpose qkv [b][1536][n] -> q/k/v [bh][n][128] ----------------
// grid: (NSP/32, DH/32, B*12), block (32,8)
__global__ void transpose_qkv_kernel(const float* __restrict__ qkv,
                                     float* __restrict__ q,
                                     float* __restrict__ k,
                                     float* __restrict__ v)
{
    __shared__ float tile[32][33];
    int z = blockIdx.z;
    int b = z / 12, r = z % 12;
    int w = r / NH, hh = r % NH;
    const float* in = qkv + ((size_t)b*QKV_C + (size_t)w*C + (size_t)hh*DH) * NSP;
    float* outp = (w == 0 ? q : (w == 1 ? k : v)) + ((size_t)(b*NH + hh)) * NSP * DH;
    int d0 = blockIdx.y * 32, n0 = blockIdx.x * 32;
    int tx = threadIdx.x;
    for (int i = threadIdx.y; i < 32; i += 8)
        tile[i][tx] = in[(size_t)(d0+i)*NSP + n0 + tx];
    __syncthreads();
    for (int i = threadIdx.y; i < 32; i += 8)
        outp[(size_t)(n0+i)*DH + d0 + tx] = tile[tx][i];
}

// ---------------- transpose o [bh][n][128] -> att [b][c][n] ----------------
// grid: (DH/32, NSP/32, B*NH), block (32,8)
__global__ void transpose_o_kernel(const float* __restrict__ o, float* __restrict__ att)
{
    __shared__ float tile[32][33];
    int z = blockIdx.z;
    int b = z / NH, hh = z % NH;
    const float* in = o + (size_t)z * NSP * DH;
    float* outp = att + ((size_t)b*C + (size_t)hh*DH) * NSP;
    int n0 = blockIdx.y * 32, d0 = blockIdx.x * 32;
    int tx = threadIdx.x;
    for (int i = threadIdx.y; i < 32; i += 8)
        tile[i][tx] = in[(size_t)(n0+i)*DH + d0 + tx];
    __syncthreads();
    for (int i = threadIdx.y; i < 32; i += 8)
        outp[(size_t)(d0+i)*NSP + n0 + tx] = tile[tx][i];
}

// ---------------- row softmax over S [rows][1024] ----------------
__global__ __launch_bounds__(256) void softmax_kernel(float* __restrict__ S)
{
    float* p = S + (size_t)blockIdx.x * NSP;
    int t = threadIdx.x;
    float4 v = *(float4*)&p[t*4];
    __shared__ float red[256];

    float m = fmaxf(fmaxf(v.x, v.y), fmaxf(v.z, v.w));
    red[t] = m;
    __syncthreads();
    for (int s = 128; s > 0; s >>= 1) {
        if (t < s) red[t] = fmaxf(red[t], red[t+s]);
        __syncthreads();
    }
    m = red[0];
    __syncthreads();

    float e0 = expf(v.x - m), e1 = expf(v.y - m);
    float e2 = expf(v.z - m), e3 = expf(v.w - m);
    red[t] = e0 + e1 + e2 + e3;
    __syncthreads();
    for (int s = 128; s > 0; s >>= 1) {
        if (t < s) red[t] += red[t+s];
        __syncthreads();
    }
    float inv = 1.f / red[0];
    v.x = e0*inv; v.y = e1*inv; v.z = e2*inv; v.w = e3*inv;
    *(float4*)&p[t*4] = v;
}

// ---------------- launch ----------------
extern "C" void kernel_launch(void* const* d_in, const int* in_sizes, int n_in,
                              void* d_out, int out_size)
{
    const float* x      = (const float*)d_in[0];
    const float* gamma  = (const float*)d_in[1];
    const float* beta   = (const float*)d_in[2];
    const float* qkv_w  = (const float*)d_in[3];
    const float* qkv_b  = (const float*)d_in[4];
    const float* proj_w = (const float*)d_in[5];
    const float* proj_b = (const float*)d_in[6];
    float* out = (float*)d_out;

    float *xn, *qkv, *q, *k, *v, *S, *o, *att;
    cudaGetSymbolAddress((void**)&xn,  g_xn);
    cudaGetSymbolAddress((void**)&qkv, g_qkv);
    cudaGetSymbolAddress((void**)&q,   g_q);
    cudaGetSymbolAddress((void**)&k,   g_k);
    cudaGetSymbolAddress((void**)&v,   g_v);
    cudaGetSymbolAddress((void**)&S,   g_S);
    cudaGetSymbolAddress((void**)&o,   g_o);
    cudaGetSymbolAddress((void**)&att, g_att);

    // 1) GroupNorm
    gn_kernel<<<B*NG, 256>>>(x, gamma, beta, xn);

    // 2) QKV: [1536,512] @ [512,1024] per batch (+bias)
    gemm_nn<<<dim3(NSP/NT, QKV_C/MT, B), 256>>>(
        qkv_w, 0, xn, (long long)C*NSP, qkv, (long long)QKV_C*NSP,
        QKV_C, NSP, C, qkv_b, nullptr, 0, 1.f);

    // 3) split + transpose into per-head [n][d]
    transpose_qkv_kernel<<<dim3(NSP/32, DH/32, B*12), dim3(32,8)>>>(qkv, q, k, v);

    // 4) S = scale * Q @ K^T per (b,h)
    gemm_nt<<<dim3(NSP/NT, NSP/MT, B*NH), 256>>>(
        q, (long long)NSP*DH, k, (long long)NSP*DH, S, (long long)NSP*NSP,
        NSP, NSP, DH, 0.08838834764831845f);

    // 5) row softmax
    softmax_kernel<<<B*NH*NSP, 256>>>(S);

    // 6) O = P @ V per (b,h)
    gemm_nn<<<dim3(DH/NT, NSP/MT, B*NH), 256>>>(
        S, (long long)NSP*NSP, v, (long long)NSP*DH, o, (long long)NSP*DH,
        NSP, DH, NSP, nullptr, nullptr, 0, 1.f);

    // 7) transpose O back to [b][c][n]
    transpose_o_kernel<<<dim3(DH/32, NSP/32, B*NH), dim3(32,8)>>>(o, att);

    // 8) proj + bias + residual
    gemm_nn<<<dim3(NSP/NT, C/MT, B), 256>>>(
        proj_w, 0, att, (long long)C*NSP, out, (long long)C*NSP,
        C, NSP, C, proj_b, x, (long long)C*NSP, 1.f);
}

// round 3
// speedup vs baseline: 1.8145x; 1.8145x over previous
#include <cuda_runtime.h>
#include <cuda_bf16.h>
#include <math.h>
#include <stdint.h>

#define B   16
#define C   512
#define NSP 1024
#define NH  4
#define DH  128
#define NG  8

// ---------------- scratch ----------------
__device__ float g_xnT [(size_t)B*NSP*C];        // [b][n][c]
__device__ float g_qkvT[(size_t)B*NSP*3*C];      // [b][n][o]
__device__ float g_vT  [(size_t)B*NH*DH*NSP];    // [bh][d][m]
__device__ float g_S   [(size_t)B*NH*NSP*NSP];   // [bh][n][m]
__device__ float g_att [(size_t)B*NSP*C];        // [b][n][c]

// ---------------- helpers ----------------
__device__ __forceinline__ uint32_t smem_u32(const void* p) {
    uint32_t a;
    asm("{ .reg .u64 t; cvta.to.shared.u64 t, %1; cvt.u32.u64 %0, t; }" : "=r"(a) : "l"(p));
    return a;
}
__device__ __forceinline__ void ldsm4(uint32_t* r, uint32_t a) {
    asm volatile("ldmatrix.sync.aligned.m8n8.x4.shared.b16 {%0,%1,%2,%3}, [%4];"
        : "=r"(r[0]), "=r"(r[1]), "=r"(r[2]), "=r"(r[3]) : "r"(a));
}
__device__ __forceinline__ void mma16816(float* d, const uint32_t* a, uint32_t b0, uint32_t b1) {
    asm volatile("mma.sync.aligned.m16n8k16.row.col.f32.bf16.bf16.f32 "
        "{%0,%1,%2,%3}, {%4,%5,%6,%7}, {%8,%9}, {%0,%1,%2,%3};"
        : "+f"(d[0]), "+f"(d[1]), "+f"(d[2]), "+f"(d[3])
        : "r"(a[0]), "r"(a[1]), "r"(a[2]), "r"(a[3]), "r"(b0), "r"(b1));
}
__device__ __forceinline__ uint32_t sw128(uint32_t off) { return off ^ ((off >> 3) & 0x70); }

// float4 -> bf16 hi/lo pairs, swizzled store (hi at sm, lo at sm+16384)
__device__ __forceinline__ void cvt_sts(float4 v, char* sm, uint32_t off) {
    __nv_bfloat16 h0 = __float2bfloat16(v.x), h1 = __float2bfloat16(v.y);
    __nv_bfloat16 h2 = __float2bfloat16(v.z), h3 = __float2bfloat16(v.w);
    __nv_bfloat16 l0 = __float2bfloat16(v.x - __bfloat162float(h0));
    __nv_bfloat16 l1 = __float2bfloat16(v.y - __bfloat162float(h1));
    __nv_bfloat16 l2 = __float2bfloat16(v.z - __bfloat162float(h2));
    __nv_bfloat16 l3 = __float2bfloat16(v.w - __bfloat162float(h3));
    uint32_t s = sw128(off);
    uint32_t hp0 = (uint32_t)__bfloat16_as_ushort(h0) | ((uint32_t)__bfloat16_as_ushort(h1) << 16);
    uint32_t hp1 = (uint32_t)__bfloat16_as_ushort(h2) | ((uint32_t)__bfloat16_as_ushort(h3) << 16);
    uint32_t lp0 = (uint32_t)__bfloat16_as_ushort(l0) | ((uint32_t)__bfloat16_as_ushort(l1) << 16);
    uint32_t lp1 = (uint32_t)__bfloat16_as_ushort(l2) | ((uint32_t)__bfloat16_as_ushort(l3) << 16);
    *(uint2*)(sm + s)         = make_uint2(hp0, hp1);
    *(uint2*)(sm + 16384 + s) = make_uint2(lp0, lp1);
}

// ---------------- HMMA GEMM: C[M,N] = alpha * A[M,K] @ B[N,K]^T (+bias)(+res) ----------------
// grid (N/128, M/128, Z), 256 threads. smem: 1024 align + 2 * 64KB (Ahi,Alo,Bhi,Blo bf16 128x64).
__global__ __launch_bounds__(256) void gemm_mma(
    const float* __restrict__ A, long long lda, long long sAb, long long sAh,
    const float* __restrict__ Bm, long long ldb, long long sBb, long long sBh,
    float* __restrict__ Cm, long long ldc, long long sCb, long long sCh,
    int K, int zdiv,
    const float* __restrict__ bias_n, const float* __restrict__ bias_m,
    const float* __restrict__ res, long long ldr, long long sRb,
    float alpha)
{
    extern __shared__ char dsm[];
    char* base = (char*)((((uintptr_t)dsm) + 1023) & ~(uintptr_t)1023);
    const int tid = threadIdx.x, lane = tid & 31, wid = tid >> 5;

    int z = blockIdx.z, bb = z / zdiv, hh = z % zdiv;
    A  += (size_t)bb * sAb + (size_t)hh * sAh;
    Bm += (size_t)bb * sBb + (size_t)hh * sBh;
    Cm += (size_t)bb * sCb + (size_t)hh * sCh;
    if (res) res += (size_t)bb * sRb;

    const int m0 = blockIdx.y * 128, n0 = blockIdx.x * 128;
    const float* Atile = A + (size_t)m0 * lda;
    const float* Btile = Bm + (size_t)n0 * ldb;

    const int warp_m = (wid >> 1) * 32;   // 4 warps along M
    const int warp_n = (wid & 1) * 64;    // 2 warps along N
    const int lr = (lane & 7) + 8 * ((lane >> 3) & 1);
    const int lc = 16 * (lane >> 4);
    const uint32_t rA0 = (uint32_t)(warp_m + lr) * 128u;
    const uint32_t rA1 = (uint32_t)(warp_m + 16 + lr) * 128u;
    const uint32_t rB0 = (uint32_t)(warp_n + lr) * 128u;
    const uint32_t rB1 = (uint32_t)(warp_n + 16 + lr) * 128u;
    const uint32_t rB2 = (uint32_t)(warp_n + 32 + lr) * 128u;
    const uint32_t rB3 = (uint32_t)(warp_n + 48 + lr) * 128u;

    const uint32_t sbase = smem_u32(base);

    float acc[2][8][4] = {};

    // initial load: chunk 0 -> buffer 0
    {
        int q = tid & 15, r0 = tid >> 4;
#pragma unroll
        for (int it = 0; it < 8; it++) {
            int r = r0 + it * 16;
            float4 va = *(const float4*)(Atile + (size_t)r * lda + q * 4);
            cvt_sts(va, base, (uint32_t)(r * 128 + q * 8));
            float4 vb = *(const float4*)(Btile + (size_t)r * ldb + q * 4);
            cvt_sts(vb, base + 32768, (uint32_t)(r * 128 + q * 8));
        }
    }
    __syncthreads();

    const int nk = K / 64;
    float4 pf[16];
    for (int i = 0; i < nk; i++) {
        int p = i & 1;
        if (i + 1 < nk) {
            int q = tid & 15, r0 = tid >> 4;
            const float* An = Atile + (i + 1) * 64 + q * 4;
            const float* Bn = Btile + (i + 1) * 64 + q * 4;
#pragma unroll
            for (int it = 0; it < 8; it++) {
                pf[it]     = *(const float4*)(An + (size_t)(r0 + it * 16) * lda);
                pf[8 + it] = *(const float4*)(Bn + (size_t)(r0 + it * 16) * ldb);
            }
        }
        uint32_t bufA = sbase + (uint32_t)p * 65536u;
        uint32_t bufB = bufA + 32768u;
#pragma unroll
        for (int kk = 0; kk < 4; kk++) {
            uint32_t kof = 32u * kk + lc;
            uint32_t ah0[4], ah1[4], al0[4], al1[4];
            ldsm4(ah0, bufA + sw128(rA0 + kof));
            ldsm4(ah1, bufA + sw128(rA1 + kof));
            ldsm4(al0, bufA + 16384u + sw128(rA0 + kof));
            ldsm4(al1, bufA + 16384u + sw128(rA1 + kof));
            uint32_t bh[4][4], bl[4][4];
            ldsm4(bh[0], bufB + sw128(rB0 + kof));
            ldsm4(bh[1], bufB + sw128(rB1 + kof));
            ldsm4(bh[2], bufB + sw128(rB2 + kof));
            ldsm4(bh[3], bufB + sw128(rB3 + kof));
            ldsm4(bl[0], bufB + 16384u + sw128(rB0 + kof));
            ldsm4(bl[1], bufB + 16384u + sw128(rB1 + kof));
            ldsm4(bl[2], bufB + 16384u + sw128(rB2 + kof));
            ldsm4(bl[3], bufB + 16384u + sw128(rB3 + kof));
#pragma unroll
            for (int j = 0; j < 8; j++) {
                int nt2 = j >> 1, t = j & 1;
                uint32_t b0 = bh[nt2][t], b1 = bh[nt2][t + 2];
                uint32_t c0 = bl[nt2][t], c1 = bl[nt2][t + 2];
                mma16816(acc[0][j], ah0, b0, b1);
                mma16816(acc[1][j], ah1, b0, b1);
                mma16816(acc[0][j], al0, b0, b1);
                mma16816(acc[1][j], al1, b0, b1);
                mma16816(acc[0][j], ah0, c0, c1);
                mma16816(acc[1][j], ah1, c0, c1);
            }
        }
        if (i + 1 < nk) {
            int q = tid & 15, r0 = tid >> 4;
            char* nb = base + (p ^ 1) * 65536;
#pragma unroll
            for (int it = 0; it < 8; it++) {
                uint32_t off = (uint32_t)((r0 + it * 16) * 128 + q * 8);
                cvt_sts(pf[it],     nb,         off);
                cvt_sts(pf[8 + it], nb + 32768, off);
            }
        }
        __syncthreads();
    }

    // epilogue: direct fp32 stores (float2 per fragment pair)
    const int er = lane >> 2, ec = (lane & 3) * 2;
#pragma unroll
    for (int mt = 0; mt < 2; mt++) {
#pragma unroll
        for (int half = 0; half < 2; half++) {
            int m = m0 + warp_m + mt * 16 + er + half * 8;
            float bm_ = bias_m ? bias_m[m] : 0.f;
#pragma unroll
            for (int j = 0; j < 8; j++) {
                int n = n0 + warp_n + j * 8 + ec;
                float v0 = alpha * acc[mt][j][half * 2 + 0] + bm_;
                float v1 = alpha * acc[mt][j][half * 2 + 1] + bm_;
                if (bias_n) { v0 += bias_n[n]; v1 += bias_n[n + 1]; }
                if (res) { const float* rp = res + (size_t)m * ldr + n; v0 += rp[0]; v1 += rp[1]; }
                *(float2*)&Cm[(size_t)m * ldc + n] = make_float2(v0, v1);
            }
        }
    }
}

// ---------------- GroupNorm -> transposed [b][n][c] ----------------
__global__ __launch_bounds__(256) void gn_t_kernel(
    const float* __restrict__ x, const float* __restrict__ gamma,
    const float* __restrict__ beta, float* __restrict__ xnT)
{
    const int CG = C / NG;          // 64
    const int GE = CG * NSP;        // 65536
    int b = blockIdx.x / NG, g = blockIdx.x % NG;
    const float* xp = x + ((size_t)b * C + (size_t)g * CG) * NSP;
    int t = threadIdx.x;

    float s = 0.f, s2 = 0.f;
    for (int i = t; i < GE; i += 256) { float v = xp[i]; s += v; s2 += v * v; }
    __shared__ float rs[256], rs2[256];
    rs[t] = s; rs2[t] = s2;
    __syncthreads();
    for (int st = 128; st > 0; st >>= 1) {
        if (t < st) { rs[t] += rs[t + st]; rs2[t] += rs2[t + st]; }
        __syncthreads();
    }
    float mu  = rs[0] * (1.f / GE);
    float var = rs2[0] * (1.f / GE) - mu * mu;
    float inv = rsqrtf(var + 1e-5f);

    __shared__ float tile[8][32][33];
    int warp = t >> 5, lane = t & 31;
    for (int tt = warp; tt < 64; tt += 8) {
        int ci = tt >> 5, ni = tt & 31;
        for (int i = 0; i < 32; i++) {
            int c = ci * 32 + i;
            int cg2 = g * CG + c;
            float v = xp[(size_t)c * NSP + ni * 32 + lane];
            tile[warp][i][lane] = (v - mu) * inv * gamma[cg2] + beta[cg2];
        }
        __syncwarp();
        for (int i = 0; i < 32; i++) {
            int n = ni * 32 + i;
            xnT[((size_t)b * NSP + n) * C + g * CG + ci * 32 + lane] = tile[warp][lane][i];
        }
        __syncwarp();
    }
}

// ---------------- vT: [bh][d][m] from qkvT [b][m][2C + h*DH + d] ----------------
__global__ void vT_kernel(const float* __restrict__ qkvT, float* __restrict__ vT)
{
    __shared__ float tile[32][33];
    int z = blockIdx.z;
    int b = z >> 2, h = z & 3;
    int m0 = blockIdx.x * 32;
    int d0 = blockIdx.y * 32;
    const float* in = qkvT + (size_t)b * NSP * (3 * C) + 2 * C + h * DH;
    int tx = threadIdx.x;
    for (int i = threadIdx.y; i < 32; i += 8)
        tile[i][tx] = in[(size_t)(m0 + i) * (3 * C) + d0 + tx];
    __syncthreads();
    float* outp = vT + (size_t)z * DH * NSP;
    for (int i = threadIdx.y; i < 32; i += 8)
        outp[(size_t)(d0 + i) * NSP + m0 + tx] = tile[tx][i];
}

// ---------------- row softmax over S [rows][1024] ----------------
__global__ __launch_bounds__(256) void softmax_kernel(float* __restrict__ S)
{
    float* p = S + (size_t)blockIdx.x * NSP;
    int t = threadIdx.x;
    float4 v = *(float4*)&p[t * 4];
    __shared__ float red[256];

    float m = fmaxf(fmaxf(v.x, v.y), fmaxf(v.z, v.w));
    red[t] = m;
    __syncthreads();
    for (int s = 128; s > 0; s >>= 1) {
        if (t < s) red[t] = fmaxf(red[t], red[t + s]);
        __syncthreads();
    }
    m = red[0];
    __syncthreads();

    float e0 = __expf(v.x - m), e1 = __expf(v.y - m);
    float e2 = __expf(v.z - m), e3 = __expf(v.w - m);
    red[t] = e0 + e1 + e2 + e3;
    __syncthreads();
    for (int s = 128; s > 0; s >>= 1) {
        if (t < s) red[t] += red[t + s];
        __syncthreads();
    }
    float inv = 1.f / red[0];
    v.x = e0 * inv; v.y = e1 * inv; v.z = e2 * inv; v.w = e3 * inv;
    *(float4*)&p[t * 4] = v;
}

// ---------------- launch ----------------
extern "C" void kernel_launch(void* const* d_in, const int* in_sizes, int n_in,
                              void* d_out, int out_size)
{
    const float* x      = (const float*)d_in[0];
    const float* gamma  = (const float*)d_in[1];
    const float* beta   = (const float*)d_in[2];
    const float* qkv_w  = (const float*)d_in[3];
    const float* qkv_b  = (const float*)d_in[4];
    const float* proj_w = (const float*)d_in[5];
    const float* proj_b = (const float*)d_in[6];
    float* out = (float*)d_out;

    float *xnT, *qkvT, *vT, *S, *att;
    cudaGetSymbolAddress((void**)&xnT,  g_xnT);
    cudaGetSymbolAddress((void**)&qkvT, g_qkvT);
    cudaGetSymbolAddress((void**)&vT,   g_vT);
    cudaGetSymbolAddress((void**)&S,    g_S);
    cudaGetSymbolAddress((void**)&att,  g_att);

    const int DSM = 1024 + 2 * 65536;   // 132096
    cudaFuncSetAttribute(gemm_mma, cudaFuncAttributeMaxDynamicSharedMemorySize, DSM);

    // 1) GroupNorm -> xnT [b][n][c]
    gn_t_kernel<<<B * NG, 256>>>(x, gamma, beta, xnT);

    // 2) qkvT[b][n][o] = xnT[b][n][:] @ qkv_w[o][:]^T + qkv_b[o]
    gemm_mma<<<dim3(12, 8, B), 256, DSM>>>(
        xnT, C, (long long)NSP * C, 0,
        qkv_w, C, 0, 0,
        qkvT, 3 * C, (long long)NSP * 3 * C, 0,
        C, 1, qkv_b, nullptr, nullptr, 0, 0, 1.f);

    // 3) vT [bh][d][m]
    vT_kernel<<<dim3(32, 4, B * NH), dim3(32, 8)>>>(qkvT, vT);

    // 4) S[bh][n][m] = scale * Q @ K^T
    gemm_mma<<<dim3(8, 8, B * NH), 256, DSM>>>(
        qkvT, 3 * C, (long long)NSP * 3 * C, DH,
        qkvT + C, 3 * C, (long long)NSP * 3 * C, DH,
        S, NSP, (long long)NH * NSP * NSP, (long long)NSP * NSP,
        DH, NH, nullptr, nullptr, nullptr, 0, 0, 0.08838834764831845f);

    // 5) softmax rows
    softmax_kernel<<<B * NH * NSP, 256>>>(S);

    // 6) att[b][n][h*DH + d] = P @ V
    gemm_mma<<<dim3(1, 8, B * NH), 256, DSM>>>(
        S, NSP, (long long)NH * NSP * NSP, (long long)NSP * NSP,
        vT, NSP, (long long)NH * DH * NSP, (long long)DH * NSP,
        att, C, (long long)NSP * C, DH,
        NSP, NH, nullptr, nullptr, nullptr, 0, 0, 1.f);

    // 7) out[b][c][n] = proj_w @ att^T + proj_b + x
    gemm_mma<<<dim3(8, 4, B), 256, DSM>>>(
        proj_w, C, 0, 0,
        att, C, (long long)NSP * C, 0,
        out, NSP, (long long)C * NSP, 0,
        C, 1, nullptr, proj_b, x, NSP, (long long)C * NSP, 1.f);
}

// round 4
// speedup vs baseline: 2.3905x; 1.3174x over previous
#include <cuda_runtime.h>
#include <cuda_bf16.h>
#include <math.h>
#include <stdint.h>

#define B   16
#define C   512
#define NSP 1024
#define NH  4
#define DH  128
#define NG  8
#define SCALE 0.08838834764831845f

// ---------------- scratch ----------------
__device__ float g_xnT [(size_t)B*NSP*C];           // [b][n][c]
__device__ float g_qkvT[(size_t)B*NSP*3*C];         // [b][n][o]
__device__ float g_att [(size_t)B*NSP*C];           // [b][n][c]
// K/V bf16 hi/lo planes, tiled: [bh][8 chunks][2 panels][128 rows][64 cols]
__device__ __nv_bfloat16 g_Kh[(size_t)B*NH*NSP*DH];
__device__ __nv_bfloat16 g_Kl[(size_t)B*NH*NSP*DH];
__device__ __nv_bfloat16 g_Vh[(size_t)B*NH*NSP*DH];
__device__ __nv_bfloat16 g_Vl[(size_t)B*NH*NSP*DH];

// ---------------- helpers ----------------
__device__ __forceinline__ uint32_t smem_u32(const void* p) {
    uint32_t a;
    asm("{ .reg .u64 t; cvta.to.shared.u64 t, %1; cvt.u32.u64 %0, t; }" : "=r"(a) : "l"(p));
    return a;
}
__device__ __forceinline__ void ldsm4(uint32_t* r, uint32_t a) {
    asm volatile("ldmatrix.sync.aligned.m8n8.x4.shared.b16 {%0,%1,%2,%3}, [%4];"
        : "=r"(r[0]), "=r"(r[1]), "=r"(r[2]), "=r"(r[3]) : "r"(a));
}
__device__ __forceinline__ void mma16816(float* d, const uint32_t* a, uint32_t b0, uint32_t b1) {
    asm volatile("mma.sync.aligned.m16n8k16.row.col.f32.bf16.bf16.f32 "
        "{%0,%1,%2,%3}, {%4,%5,%6,%7}, {%8,%9}, {%0,%1,%2,%3};"
        : "+f"(d[0]), "+f"(d[1]), "+f"(d[2]), "+f"(d[3])
        : "r"(a[0]), "r"(a[1]), "r"(a[2]), "r"(a[3]), "r"(b0), "r"(b1));
}
__device__ __forceinline__ uint32_t sw128(uint32_t off) { return off ^ ((off >> 3) & 0x70); }
__device__ __forceinline__ uint32_t pk2(float lo, float hi) {
    uint32_t r;
    asm("cvt.rn.bf16x2.f32 %0, %1, %2;" : "=r"(r) : "f"(hi), "f"(lo));
    return r;
}
__device__ __forceinline__ float lo16f(uint32_t u) { return __uint_as_float(u << 16); }
__device__ __forceinline__ float hi16f(uint32_t u) { return __uint_as_float(u & 0xFFFF0000u); }

#define CPA16(dst, src) asm volatile("cp.async.cg.shared.global [%0], [%1], 16;" :: "r"(dst), "l"(src))
#define CPCOMMIT() asm volatile("cp.async.commit_group;" ::: "memory")
#define CPWAIT1()  asm volatile("cp.async.wait_group 1;" ::: "memory")

// fp32x4 -> bf16 hi/lo (lo plane at +32768 from hi base)
__device__ __forceinline__ void sts_hl(char* hib, uint32_t swoff, float4 v) {
    __nv_bfloat16 h0 = __float2bfloat16(v.x), h1 = __float2bfloat16(v.y);
    __nv_bfloat16 h2 = __float2bfloat16(v.z), h3 = __float2bfloat16(v.w);
    __nv_bfloat16 l0 = __float2bfloat16(v.x - __bfloat162float(h0));
    __nv_bfloat16 l1 = __float2bfloat16(v.y - __bfloat162float(h1));
    __nv_bfloat16 l2 = __float2bfloat16(v.z - __bfloat162float(h2));
    __nv_bfloat16 l3 = __float2bfloat16(v.w - __bfloat162float(h3));
    uint32_t hp0 = (uint32_t)__bfloat16_as_ushort(h0) | ((uint32_t)__bfloat16_as_ushort(h1) << 16);
    uint32_t hp1 = (uint32_t)__bfloat16_as_ushort(h2) | ((uint32_t)__bfloat16_as_ushort(h3) << 16);
    uint32_t lp0 = (uint32_t)__bfloat16_as_ushort(l0) | ((uint32_t)__bfloat16_as_ushort(l1) << 16);
    uint32_t lp1 = (uint32_t)__bfloat16_as_ushort(l2) | ((uint32_t)__bfloat16_as_ushort(l3) << 16);
    *(uint2*)(hib + swoff)         = make_uint2(hp0, hp1);
    *(uint2*)(hib + 32768 + swoff) = make_uint2(lp0, lp1);
}

// ---------------- HMMA GEMM (unchanged from R3): C = alpha*A@B^T (+bias)(+res) ----------------
__device__ __forceinline__ void cvt_sts(float4 v, char* sm, uint32_t off) {
    __nv_bfloat16 h0 = __float2bfloat16(v.x), h1 = __float2bfloat16(v.y);
    __nv_bfloat16 h2 = __float2bfloat16(v.z), h3 = __float2bfloat16(v.w);
    __nv_bfloat16 l0 = __float2bfloat16(v.x - __bfloat162float(h0));
    __nv_bfloat16 l1 = __float2bfloat16(v.y - __bfloat162float(h1));
    __nv_bfloat16 l2 = __float2bfloat16(v.z - __bfloat162float(h2));
    __nv_bfloat16 l3 = __float2bfloat16(v.w - __bfloat162float(h3));
    uint32_t s = sw128(off);
    uint32_t hp0 = (uint32_t)__bfloat16_as_ushort(h0) | ((uint32_t)__bfloat16_as_ushort(h1) << 16);
    uint32_t hp1 = (uint32_t)__bfloat16_as_ushort(h2) | ((uint32_t)__bfloat16_as_ushort(h3) << 16);
    uint32_t lp0 = (uint32_t)__bfloat16_as_ushort(l0) | ((uint32_t)__bfloat16_as_ushort(l1) << 16);
    uint32_t lp1 = (uint32_t)__bfloat16_as_ushort(l2) | ((uint32_t)__bfloat16_as_ushort(l3) << 16);
    *(uint2*)(sm + s)         = make_uint2(hp0, hp1);
    *(uint2*)(sm + 16384 + s) = make_uint2(lp0, lp1);
}

__global__ __launch_bounds__(256) void gemm_mma(
    const float* __restrict__ A, long long lda, long long sAb, long long sAh,
    const float* __restrict__ Bm, long long ldb, long long sBb, long long sBh,
    float* __restrict__ Cm, long long ldc, long long sCb, long long sCh,
    int K, int zdiv,
    const float* __restrict__ bias_n, const float* __restrict__ bias_m,
    const float* __restrict__ res, long long ldr, long long sRb,
    float alpha)
{
    extern __shared__ char dsm[];
    char* base = (char*)((((uintptr_t)dsm) + 1023) & ~(uintptr_t)1023);
    const int tid = threadIdx.x, lane = tid & 31, wid = tid >> 5;

    int z = blockIdx.z, bb = z / zdiv, hh = z % zdiv;
    A  += (size_t)bb * sAb + (size_t)hh * sAh;
    Bm += (size_t)bb * sBb + (size_t)hh * sBh;
    Cm += (size_t)bb * sCb + (size_t)hh * sCh;
    if (res) res += (size_t)bb * sRb;

    const int m0 = blockIdx.y * 128, n0 = blockIdx.x * 128;
    const float* Atile = A + (size_t)m0 * lda;
    const float* Btile = Bm + (size_t)n0 * ldb;

    const int warp_m = (wid >> 1) * 32;
    const int warp_n = (wid & 1) * 64;
    const int lr = (lane & 7) + 8 * ((lane >> 3) & 1);
    const int lc = 16 * (lane >> 4);
    const uint32_t rA0 = (uint32_t)(warp_m + lr) * 128u;
    const uint32_t rA1 = (uint32_t)(warp_m + 16 + lr) * 128u;
    const uint32_t rB0 = (uint32_t)(warp_n + lr) * 128u;
    const uint32_t rB1 = (uint32_t)(warp_n + 16 + lr) * 128u;
    const uint32_t rB2 = (uint32_t)(warp_n + 32 + lr) * 128u;
    const uint32_t rB3 = (uint32_t)(warp_n + 48 + lr) * 128u;

    const uint32_t sbase = smem_u32(base);
    float acc[2][8][4] = {};

    {
        int q = tid & 15, r0 = tid >> 4;
#pragma unroll
        for (int it = 0; it < 8; it++) {
            int r = r0 + it * 16;
            float4 va = *(const float4*)(Atile + (size_t)r * lda + q * 4);
            cvt_sts(va, base, (uint32_t)(r * 128 + q * 8));
            float4 vb = *(const float4*)(Btile + (size_t)r * ldb + q * 4);
            cvt_sts(vb, base + 32768, (uint32_t)(r * 128 + q * 8));
        }
    }
    __syncthreads();

    const int nk = K / 64;
    float4 pf[16];
    for (int i = 0; i < nk; i++) {
        int p = i & 1;
        if (i + 1 < nk) {
            int q = tid & 15, r0 = tid >> 4;
            const float* An = Atile + (i + 1) * 64 + q * 4;
            const float* Bn = Btile + (i + 1) * 64 + q * 4;
#pragma unroll
            for (int it = 0; it < 8; it++) {
                pf[it]     = *(const float4*)(An + (size_t)(r0 + it * 16) * lda);
                pf[8 + it] = *(const float4*)(Bn + (size_t)(r0 + it * 16) * ldb);
            }
        }
        uint32_t bufA = sbase + (uint32_t)p * 65536u;
        uint32_t bufB = bufA + 32768u;
#pragma unroll
        for (int kk = 0; kk < 4; kk++) {
            uint32_t kof = 32u * kk + lc;
            uint32_t ah0[4], ah1[4], al0[4], al1[4];
            ldsm4(ah0, bufA + sw128(rA0 + kof));
            ldsm4(ah1, bufA + sw128(rA1 + kof));
            ldsm4(al0, bufA + 16384u + sw128(rA0 + kof));
            ldsm4(al1, bufA + 16384u + sw128(rA1 + kof));
            uint32_t bh[4][4], bl[4][4];
            ldsm4(bh[0], bufB + sw128(rB0 + kof));
            ldsm4(bh[1], bufB + sw128(rB1 + kof));
            ldsm4(bh[2], bufB + sw128(rB2 + kof));
            ldsm4(bh[3], bufB + sw128(rB3 + kof));
            ldsm4(bl[0], bufB + 16384u + sw128(rB0 + kof));
            ldsm4(bl[1], bufB + 16384u + sw128(rB1 + kof));
            ldsm4(bl[2], bufB + 16384u + sw128(rB2 + kof));
            ldsm4(bl[3], bufB + 16384u + sw128(rB3 + kof));
#pragma unroll
            for (int j = 0; j < 8; j++) {
                int nt2 = j >> 1, t = j & 1;
                uint32_t b0 = bh[nt2][t], b1 = bh[nt2][t + 2];
                uint32_t c0 = bl[nt2][t], c1 = bl[nt2][t + 2];
                mma16816(acc[0][j], ah0, b0, b1);
                mma16816(acc[1][j], ah1, b0, b1);
                mma16816(acc[0][j], al0, b0, b1);
                mma16816(acc[1][j], al1, b0, b1);
                mma16816(acc[0][j], ah0, c0, c1);
                mma16816(acc[1][j], ah1, c0, c1);
            }
        }
        if (i + 1 < nk) {
            int q = tid & 15, r0 = tid >> 4;
            char* nb = base + (p ^ 1) * 65536;
#pragma unroll
            for (int it = 0; it < 8; it++) {
                uint32_t off = (uint32_t)((r0 + it * 16) * 128 + q * 8);
                cvt_sts(pf[it],     nb,         off);
                cvt_sts(pf[8 + it], nb + 32768, off);
            }
        }
        __syncthreads();
    }

    const int er = lane >> 2, ec = (lane & 3) * 2;
#pragma unroll
    for (int mt = 0; mt < 2; mt++) {
#pragma unroll
        for (int half = 0; half < 2; half++) {
            int m = m0 + warp_m + mt * 16 + er + half * 8;
            float bm_ = bias_m ? bias_m[m] : 0.f;
#pragma unroll
            for (int j = 0; j < 8; j++) {
                int n = n0 + warp_n + j * 8 + ec;
                float v0 = alpha * acc[mt][j][half * 2 + 0] + bm_;
                float v1 = alpha * acc[mt][j][half * 2 + 1] + bm_;
                if (bias_n) { v0 += bias_n[n]; v1 += bias_n[n + 1]; }
                if (res) { const float* rp = res + (size_t)m * ldr + n; v0 += rp[0]; v1 += rp[1]; }
                *(float2*)&Cm[(size_t)m * ldc + n] = make_float2(v0, v1);
            }
        }
    }
}

// ---------------- GroupNorm -> transposed [b][n][c] ----------------
__global__ __launch_bounds__(256) void gn_t_kernel(
    const float* __restrict__ x, const float* __restrict__ gamma,
    const float* __restrict__ beta, float* __restrict__ xnT)
{
    const int CG = C / NG;
    const int GE = CG * NSP;
    int b = blockIdx.x / NG, g = blockIdx.x % NG;
    const float* xp = x + ((size_t)b * C + (size_t)g * CG) * NSP;
    int t = threadIdx.x;

    float s = 0.f, s2 = 0.f;
    for (int i = t; i < GE; i += 256) { float v = xp[i]; s += v; s2 += v * v; }
    __shared__ float rs[256], rs2[256];
    rs[t] = s; rs2[t] = s2;
    __syncthreads();
    for (int st = 128; st > 0; st >>= 1) {
        if (t < st) { rs[t] += rs[t + st]; rs2[t] += rs2[t + st]; }
        __syncthreads();
    }
    float mu  = rs[0] * (1.f / GE);
    float var = rs2[0] * (1.f / GE) - mu * mu;
    float inv = rsqrtf(var + 1e-5f);

    __shared__ float tile[8][32][33];
    int warp = t >> 5, lane = t & 31;
    for (int tt = warp; tt < 64; tt += 8) {
        int ci = tt >> 5, ni = tt & 31;
        for (int i = 0; i < 32; i++) {
            int c = ci * 32 + i;
            int cg2 = g * CG + c;
            float v = xp[(size_t)c * NSP + ni * 32 + lane];
            tile[warp][i][lane] = (v - mu) * inv * gamma[cg2] + beta[cg2];
        }
        __syncwarp();
        for (int i = 0; i < 32; i++) {
            int n = ni * 32 + i;
            xnT[((size_t)b * NSP + n) * C + g * CG + ci * 32 + lane] = tile[warp][lane][i];
        }
        __syncwarp();
    }
}

// ---------------- K convert: qkvT[+C] fp32 -> tiled bf16 hi/lo planes ----------------
// grid B*NH*8, 256 thr.  plane layout per (bh,chunk): [2 panels][128 rows][64 cols]
__global__ __launch_bounds__(256) void khl_kernel(const float* __restrict__ qkvT,
                                                  __nv_bfloat16* __restrict__ Kh,
                                                  __nv_bfloat16* __restrict__ Kl)
{
    int zz = blockIdx.x;
    int bh = zz >> 3, mc = zz & 7;
    int b = bh >> 2, h = bh & 3;
    const float* src = qkvT + ((size_t)b * NSP + mc * 128) * (3 * C) + C + h * DH;
    __nv_bfloat16* dh = Kh + (size_t)zz * 16384;
    __nv_bfloat16* dl = Kl + (size_t)zz * 16384;
    for (int idx = threadIdx.x; idx < 4096; idx += 256) {
        int r = idx >> 5, c4 = idx & 31;
        float4 v = *(const float4*)(src + (size_t)r * (3 * C) + c4 * 4);
        int d0 = c4 * 4, p = d0 >> 6, cc = d0 & 63;
        int o = p * 8192 + r * 64 + cc;
        __nv_bfloat16 h0 = __float2bfloat16(v.x), h1 = __float2bfloat16(v.y);
        __nv_bfloat16 h2 = __float2bfloat16(v.z), h3 = __float2bfloat16(v.w);
        dh[o] = h0; dh[o+1] = h1; dh[o+2] = h2; dh[o+3] = h3;
        dl[o]   = __float2bfloat16(v.x - __bfloat162float(h0));
        dl[o+1] = __float2bfloat16(v.y - __bfloat162float(h1));
        dl[o+2] = __float2bfloat16(v.z - __bfloat162float(h2));
        dl[o+3] = __float2bfloat16(v.w - __bfloat162float(h3));
    }
}

// ---------------- V convert+transpose: qkvT[+2C] -> Vh/Vl [bh][chunk][2 p][128 d][64 kv] ----------------
__global__ __launch_bounds__(256) void vhl_kernel(const float* __restrict__ qkvT,
                                                  __nv_bfloat16* __restrict__ Vh,
                                                  __nv_bfloat16* __restrict__ Vl)
{
    extern __shared__ float vt[];   // [128][129]
    int zz = blockIdx.x;
    int bh = zz >> 3, mc = zz & 7;
    int b = bh >> 2, h = bh & 3;
    const float* src = qkvT + ((size_t)b * NSP + mc * 128) * (3 * C) + 2 * C + h * DH;
    for (int idx = threadIdx.x; idx < 4096; idx += 256) {
        int r = idx >> 5, c4 = idx & 31;
        float4 v = *(const float4*)(src + (size_t)r * (3 * C) + c4 * 4);
        float* tp = vt + r * 129 + c4 * 4;
        tp[0] = v.x; tp[1] = v.y; tp[2] = v.z; tp[3] = v.w;
    }
    __syncthreads();
    __nv_bfloat16* dh = Vh + (size_t)zz * 16384;
    __nv_bfloat16* dl = Vl + (size_t)zz * 16384;
    for (int idx = threadIdx.x; idx < 8192; idx += 256) {
        int o2 = idx * 2;
        int p = o2 >> 13, rem = o2 & 8191;
        int d = rem >> 6, kvc = rem & 63;
        float v0 = vt[(p * 64 + kvc) * 129 + d];
        float v1 = vt[(p * 64 + kvc + 1) * 129 + d];
        __nv_bfloat16 h0 = __float2bfloat16(v0), h1 = __float2bfloat16(v1);
        dh[o2] = h0; dh[o2 + 1] = h1;
        dl[o2]     = __float2bfloat16(v0 - __bfloat162float(h0));
        dl[o2 + 1] = __float2bfloat16(v1 - __bfloat162float(h1));
    }
}

// ---------------- fused flash attention ----------------
// grid (8 qblocks, 64 bh), 256 thr. smem: Q 64KB + K 64KB + V 64KB.
#define FSM_Q 0
#define FSM_K 65536
#define FSM_V 131072

__device__ __forceinline__ void load_kv_tile(uint32_t sdst,
    const __nv_bfloat16* __restrict__ hp, const __nv_bfloat16* __restrict__ lp,
    int chunk, int tid)
{
    const char* srcH = (const char*)(hp + (size_t)chunk * 16384);
    const char* srcL = (const char*)(lp + (size_t)chunk * 16384);
#pragma unroll
    for (int p = 0; p < 2; p++) {
#pragma unroll
        for (int wv = 0; wv < 4; wv++) {
            int idx = tid + wv * 256;
            int r = idx >> 3, q = idx & 7;
            uint32_t d = sdst + p * 16384 + r * 128 + ((q ^ (r & 7)) * 16);
            CPA16(d,         srcH + p * 16384 + idx * 16);
            CPA16(d + 32768, srcL + p * 16384 + idx * 16);
        }
    }
}

__global__ __launch_bounds__(256) void flash_kernel(
    const float* __restrict__ qkvT,
    const __nv_bfloat16* __restrict__ Kh, const __nv_bfloat16* __restrict__ Kl,
    const __nv_bfloat16* __restrict__ Vh, const __nv_bfloat16* __restrict__ Vl,
    float* __restrict__ att)
{
    extern __shared__ char dsm[];
    char* base = (char*)((((uintptr_t)dsm) + 1023) & ~(uintptr_t)1023);
    const uint32_t sb = smem_u32(base);
    const int tid = threadIdx.x, lane = tid & 31, wid = tid >> 5;
    const int qb = blockIdx.x;
    const int z = blockIdx.y;
    const int b = z >> 2, h = z & 3;

    const __nv_bfloat16* KhP = Kh + (size_t)z * 8 * 16384;
    const __nv_bfloat16* KlP = Kl + (size_t)z * 8 * 16384;
    const __nv_bfloat16* VhP = Vh + (size_t)z * 8 * 16384;
    const __nv_bfloat16* VlP = Vl + (size_t)z * 8 * 16384;

    // prefetch K0, V0
    load_kv_tile(sb + FSM_K, KhP, KlP, 0, tid); CPCOMMIT();
    load_kv_tile(sb + FSM_V, VhP, VlP, 0, tid); CPCOMMIT();

    // Q prologue: fp32 -> bf16 hi/lo smem panels, scale folded
    {
        const float* Qg = qkvT + ((size_t)b * NSP + qb * 128) * (3 * C) + h * DH;
        int r = tid >> 1, hc = (tid & 1) * 64;
#pragma unroll
        for (int q4 = 0; q4 < 16; q4++) {
            int d0 = hc + q4 * 4;
            float4 v = *(const float4*)(Qg + (size_t)r * (3 * C) + d0);
            v.x *= SCALE; v.y *= SCALE; v.z *= SCALE; v.w *= SCALE;
            int p = d0 >> 6, cc = d0 & 63;
            uint32_t swoff = (uint32_t)r * 128u + ((uint32_t)(cc * 2) ^ ((r & 7) * 16));
            sts_hl(base + FSM_Q + p * 16384, swoff, v);
        }
    }
    __syncthreads();

    const int lr = (lane & 7) + 8 * ((lane >> 3) & 1);
    const uint32_t lc = 16u * (lane >> 4);
    const uint32_t qrow = 16u * wid + lr;
    const uint32_t qoff = qrow * 128u;
    const uint32_t qxor = (qrow & 7) * 16u;

    float accO[16][4] = {};
    float M0 = -1e30f, M1 = -1e30f, L0 = 0.f, L1 = 0.f;

    for (int c = 0; c < 8; c++) {
        float accS[16][4] = {};
        CPWAIT1(); __syncthreads();     // K_c ready
        // ---- QK ----
#pragma unroll
        for (int p = 0; p < 2; p++) {
#pragma unroll
            for (int kk = 0; kk < 4; kk++) {
                uint32_t kof = 32u * kk + lc;
                uint32_t qa = sb + FSM_Q + p * 16384 + qoff + (kof ^ qxor);
                uint32_t ah[4], al[4];
                ldsm4(ah, qa); ldsm4(al, qa + 32768);
#pragma unroll
                for (int nt = 0; nt < 8; nt++) {
                    uint32_t krow = nt * 16 + lr;
                    uint32_t ka = sb + FSM_K + p * 16384 + krow * 128 + (kof ^ ((krow & 7) * 16));
                    uint32_t bh_[4], bl_[4];
                    ldsm4(bh_, ka); ldsm4(bl_, ka + 32768);
                    mma16816(accS[2*nt],   ah, bh_[0], bh_[2]);
                    mma16816(accS[2*nt],   al, bh_[0], bh_[2]);
                    mma16816(accS[2*nt],   ah, bl_[0], bl_[2]);
                    mma16816(accS[2*nt+1], ah, bh_[1], bh_[3]);
                    mma16816(accS[2*nt+1], al, bh_[1], bh_[3]);
                    mma16816(accS[2*nt+1], ah, bl_[1], bl_[3]);
                }
            }
        }
        __syncthreads();                 // done reading Kbuf
        if (c + 1 < 8) load_kv_tile(sb + FSM_K, KhP, KlP, c + 1, tid);
        CPCOMMIT();
        // ---- online softmax ----
        float m0 = -1e30f, m1 = -1e30f;
#pragma unroll
        for (int j = 0; j < 16; j++) {
            m0 = fmaxf(m0, fmaxf(accS[j][0], accS[j][1]));
            m1 = fmaxf(m1, fmaxf(accS[j][2], accS[j][3]));
        }
        m0 = fmaxf(m0, __shfl_xor_sync(0xffffffffu, m0, 1));
        m0 = fmaxf(m0, __shfl_xor_sync(0xffffffffu, m0, 2));
        m1 = fmaxf(m1, __shfl_xor_sync(0xffffffffu, m1, 1));
        m1 = fmaxf(m1, __shfl_xor_sync(0xffffffffu, m1, 2));
        float nM0 = fmaxf(M0, m0), nM1 = fmaxf(M1, m1);
        float a0 = __expf(M0 - nM0), a1 = __expf(M1 - nM1);
        M0 = nM0; M1 = nM1;
        float s0 = 0.f, s1 = 0.f;
#pragma unroll
        for (int j = 0; j < 16; j++) {
            accS[j][0] = __expf(accS[j][0] - M0);
            accS[j][1] = __expf(accS[j][1] - M0);
            accS[j][2] = __expf(accS[j][2] - M1);
            accS[j][3] = __expf(accS[j][3] - M1);
            s0 += accS[j][0] + accS[j][1];
            s1 += accS[j][2] + accS[j][3];
        }
        s0 += __shfl_xor_sync(0xffffffffu, s0, 1);
        s0 += __shfl_xor_sync(0xffffffffu, s0, 2);
        s1 += __shfl_xor_sync(0xffffffffu, s1, 1);
        s1 += __shfl_xor_sync(0xffffffffu, s1, 2);
        L0 = L0 * a0 + s0;
        L1 = L1 * a1 + s1;
#pragma unroll
        for (int j = 0; j < 16; j++) {
            accO[j][0] *= a0; accO[j][1] *= a0;
            accO[j][2] *= a1; accO[j][3] *= a1;
        }
        CPWAIT1(); __syncthreads();      // V_c ready
        // ---- PV ----
#pragma unroll
        for (int p = 0; p < 2; p++) {
#pragma unroll
            for (int kk = 0; kk < 4; kk++) {
                int kt = p * 4 + kk;
                uint32_t kof = 32u * kk + lc;
                uint32_t phi[4], plo[4];
                {
                    const float* e0 = accS[2*kt];
                    const float* e1 = accS[2*kt+1];
                    phi[0] = pk2(e0[0], e0[1]);
                    phi[1] = pk2(e0[2], e0[3]);
                    phi[2] = pk2(e1[0], e1[1]);
                    phi[3] = pk2(e1[2], e1[3]);
                    plo[0] = pk2(e0[0] - lo16f(phi[0]), e0[1] - hi16f(phi[0]));
                    plo[1] = pk2(e0[2] - lo16f(phi[1]), e0[3] - hi16f(phi[1]));
                    plo[2] = pk2(e1[0] - lo16f(phi[2]), e1[1] - hi16f(phi[2]));
                    plo[3] = pk2(e1[2] - lo16f(phi[3]), e1[3] - hi16f(phi[3]));
                }
#pragma unroll
                for (int nt = 0; nt < 8; nt++) {
                    uint32_t vrow = nt * 16 + lr;
                    uint32_t va = sb + FSM_V + p * 16384 + vrow * 128 + (kof ^ ((vrow & 7) * 16));
                    uint32_t vh_[4], vl_[4];
                    ldsm4(vh_, va); ldsm4(vl_, va + 32768);
                    mma16816(accO[2*nt],   phi, vh_[0], vh_[2]);
                    mma16816(accO[2*nt],   plo, vh_[0], vh_[2]);
                    mma16816(accO[2*nt],   phi, vl_[0], vl_[2]);
                    mma16816(accO[2*nt+1], phi, vh_[1], vh_[3]);
                    mma16816(accO[2*nt+1], plo, vh_[1], vh_[3]);
                    mma16816(accO[2*nt+1], phi, vl_[1], vl_[3]);
                }
            }
        }
        __syncthreads();                 // done reading Vbuf
        if (c + 1 < 8) load_kv_tile(sb + FSM_V, VhP, VlP, c + 1, tid);
        CPCOMMIT();
    }

    // epilogue
    float i0 = 1.f / L0, i1 = 1.f / L1;
    int row0 = qb * 128 + 16 * wid + (lane >> 2);
    int ec = (lane & 3) * 2;
    float* op = att + ((size_t)b * NSP + row0) * C + h * DH;
#pragma unroll
    for (int j = 0; j < 16; j++) {
        int col = j * 8 + ec;
        *(float2*)(op + col)               = make_float2(accO[j][0] * i0, accO[j][1] * i0);
        *(float2*)(op + (size_t)8 * C + col) = make_float2(accO[j][2] * i1, accO[j][3] * i1);
    }
}

// ---------------- launch ----------------
extern "C" void kernel_launch(void* const* d_in, const int* in_sizes, int n_in,
                              void* d_out, int out_size)
{
    const float* x      = (const float*)d_in[0];
    const float* gamma  = (const float*)d_in[1];
    const float* beta   = (const float*)d_in[2];
    const float* qkv_w  = (const float*)d_in[3];
    const float* qkv_b  = (const float*)d_in[4];
    const float* proj_w = (const float*)d_in[5];
    const float* proj_b = (const float*)d_in[6];
    float* out = (float*)d_out;

    float *xnT, *qkvT, *att;
    __nv_bfloat16 *Kh, *Kl, *Vh, *Vl;
    cudaGetSymbolAddress((void**)&xnT,  g_xnT);
    cudaGetSymbolAddress((void**)&qkvT, g_qkvT);
    cudaGetSymbolAddress((void**)&att,  g_att);
    cudaGetSymbolAddress((void**)&Kh,   g_Kh);
    cudaGetSymbolAddress((void**)&Kl,   g_Kl);
    cudaGetSymbolAddress((void**)&Vh,   g_Vh);
    cudaGetSymbolAddress((void**)&Vl,   g_Vl);

    const int DSM  = 1024 + 2 * 65536;
    const int FDSM = 1024 + 3 * 65536;
    const int VDSM = 128 * 129 * 4;
    cudaFuncSetAttribute(gemm_mma,     cudaFuncAttributeMaxDynamicSharedMemorySize, DSM);
    cudaFuncSetAttribute(flash_kernel, cudaFuncAttributeMaxDynamicSharedMemorySize, FDSM);
    cudaFuncSetAttribute(vhl_kernel,   cudaFuncAttributeMaxDynamicSharedMemorySize, VDSM);

    // 1) GroupNorm -> xnT
    gn_t_kernel<<<B * NG, 256>>>(x, gamma, beta, xnT);

    // 2) QKV GEMM
    gemm_mma<<<dim3(12, 8, B), 256, DSM>>>(
        xnT, C, (long long)NSP * C, 0,
        qkv_w, C, 0, 0,
        qkvT, 3 * C, (long long)NSP * 3 * C, 0,
        C, 1, qkv_b, nullptr, nullptr, 0, 0, 1.f);

    // 3) K/V bf16 hi-lo conversion (tiled layouts)
    khl_kernel<<<B * NH * 8, 256>>>(qkvT, Kh, Kl);
    vhl_kernel<<<B * NH * 8, 256, VDSM>>>(qkvT, Vh, Vl);

    // 4) fused attention -> att [b][n][c]
    flash_kernel<<<dim3(8, B * NH), 256, FDSM>>>(qkvT, Kh, Kl, Vh, Vl, att);

    // 5) proj + bias + residual
    gemm_mma<<<dim3(8, 4, B), 256, DSM>>>(
        proj_w, C, 0, 0,
        att, C, (long long)NSP * C, 0,
        out, NSP, (long long)C * NSP, 0,
        C, 1, nullptr, proj_b, x, NSP, (long long)C * NSP, 1.f);
}

// round 5
// speedup vs baseline: 2.7670x; 1.1575x over previous
#include <cuda_runtime.h>
#include <cuda_bf16.h>
#include <math.h>
#include <stdint.h>

#define B   16
#define C   512
#define NSP 1024
#define NH  4
#define DH  128
#define NG  8
#define SCALE 0.08838834764831845f
#define SC2   (0.08838834764831845f * 1.4426950408889634f)   // scale * log2(e)

// ---------------- scratch ----------------
__device__ float g_qkvT[(size_t)B*NSP*3*C];         // [b][n][o] fp32
// bf16 hi/lo planes
__device__ __nv_bfloat16 g_xnh[(size_t)B*NSP*C];
__device__ __nv_bfloat16 g_xnl[(size_t)B*NSP*C];
__device__ __nv_bfloat16 g_qwh[(size_t)3*C*C];
__device__ __nv_bfloat16 g_qwl[(size_t)3*C*C];
__device__ __nv_bfloat16 g_pwh[(size_t)C*C];
__device__ __nv_bfloat16 g_pwl[(size_t)C*C];
__device__ __nv_bfloat16 g_atth[(size_t)B*NSP*C];
__device__ __nv_bfloat16 g_attl[(size_t)B*NSP*C];
// K/V planes, tiled: [bh][8 chunks][2 panels][128 rows][64 cols]
__device__ __nv_bfloat16 g_Kh[(size_t)B*NH*NSP*DH];
__device__ __nv_bfloat16 g_Kl[(size_t)B*NH*NSP*DH];
__device__ __nv_bfloat16 g_Vh[(size_t)B*NH*NSP*DH];
__device__ __nv_bfloat16 g_Vl[(size_t)B*NH*NSP*DH];

// ---------------- helpers ----------------
__device__ __forceinline__ uint32_t smem_u32(const void* p) {
    uint32_t a;
    asm("{ .reg .u64 t; cvta.to.shared.u64 t, %1; cvt.u32.u64 %0, t; }" : "=r"(a) : "l"(p));
    return a;
}
__device__ __forceinline__ void ldsm4(uint32_t* r, uint32_t a) {
    asm volatile("ldmatrix.sync.aligned.m8n8.x4.shared.b16 {%0,%1,%2,%3}, [%4];"
        : "=r"(r[0]), "=r"(r[1]), "=r"(r[2]), "=r"(r[3]) : "r"(a));
}
__device__ __forceinline__ void mma16816(float* d, const uint32_t* a, uint32_t b0, uint32_t b1) {
    asm volatile("mma.sync.aligned.m16n8k16.row.col.f32.bf16.bf16.f32 "
        "{%0,%1,%2,%3}, {%4,%5,%6,%7}, {%8,%9}, {%0,%1,%2,%3};"
        : "+f"(d[0]), "+f"(d[1]), "+f"(d[2]), "+f"(d[3])
        : "r"(a[0]), "r"(a[1]), "r"(a[2]), "r"(a[3]), "r"(b0), "r"(b1));
}
__device__ __forceinline__ uint32_t sw128(uint32_t off) { return off ^ ((off >> 3) & 0x70); }
__device__ __forceinline__ uint32_t pk2(float lo, float hi) {
    uint32_t r;
    asm("cvt.rn.bf16x2.f32 %0, %1, %2;" : "=r"(r) : "f"(hi), "f"(lo));
    return r;
}
__device__ __forceinline__ float lo16f(uint32_t u) { return __uint_as_float(u << 16); }
__device__ __forceinline__ float hi16f(uint32_t u) { return __uint_as_float(u & 0xFFFF0000u); }

#define CPA16(dst, src) asm volatile("cp.async.cg.shared.global [%0], [%1], 16;" :: "r"(dst), "l"(src))
#define CPCOMMIT() asm volatile("cp.async.commit_group;" ::: "memory")
#define CPWAIT1()  asm volatile("cp.async.wait_group 1;" ::: "memory")

// fp32x4 -> bf16 hi/lo (lo plane at +32768 from hi base)
__device__ __forceinline__ void sts_hl(char* hib, uint32_t swoff, float4 v) {
    __nv_bfloat16 h0 = __float2bfloat16(v.x), h1 = __float2bfloat16(v.y);
    __nv_bfloat16 h2 = __float2bfloat16(v.z), h3 = __float2bfloat16(v.w);
    __nv_bfloat16 l0 = __float2bfloat16(v.x - __bfloat162float(h0));
    __nv_bfloat16 l1 = __float2bfloat16(v.y - __bfloat162float(h1));
    __nv_bfloat16 l2 = __float2bfloat16(v.z - __bfloat162float(h2));
    __nv_bfloat16 l3 = __float2bfloat16(v.w - __bfloat162float(h3));
    uint32_t hp0 = (uint32_t)__bfloat16_as_ushort(h0) | ((uint32_t)__bfloat16_as_ushort(h1) << 16);
    uint32_t hp1 = (uint32_t)__bfloat16_as_ushort(h2) | ((uint32_t)__bfloat16_as_ushort(h3) << 16);
    uint32_t lp0 = (uint32_t)__bfloat16_as_ushort(l0) | ((uint32_t)__bfloat16_as_ushort(l1) << 16);
    uint32_t lp1 = (uint32_t)__bfloat16_as_ushort(l2) | ((uint32_t)__bfloat16_as_ushort(l3) << 16);
    *(uint2*)(hib + swoff)         = make_uint2(hp0, hp1);
    *(uint2*)(hib + 32768 + swoff) = make_uint2(lp0, lp1);
}

// ---------------- weight convert ----------------
__global__ __launch_bounds__(256) void wcvt_kernel(const float* __restrict__ src,
    __nv_bfloat16* __restrict__ dh, __nv_bfloat16* __restrict__ dl, int n)
{
    int i = blockIdx.x * 256 + threadIdx.x;
    if (i < n) {
        float v = src[i];
        __nv_bfloat16 h = __float2bfloat16(v);
        dh[i] = h;
        dl[i] = __float2bfloat16(v - __bfloat162float(h));
    }
}

// ---------------- bf16-plane HMMA GEMM: C[M,N] = alpha*A@B^T (+bias)(+res) ----------------
// A,B given as bf16 hi/lo row-major planes. grid (N/128, M/128, B). 256 thr.
// smem: 2 bufs x 64KB (Ah 16K | Al 16K | Bh 16K | Bl 16K), cp.async double buffered.
__device__ __forceinline__ void ld_plane(uint32_t sdst, const __nv_bfloat16* __restrict__ src,
                                         long long ld, int row0, int k0, int tid)
{
    const char* s = (const char*)src + ((size_t)row0 * ld + k0) * 2;
#pragma unroll
    for (int g = 0; g < 4; g++) {
        int idx = tid + g * 256;
        int r = idx >> 3, q = idx & 7;
        CPA16(sdst + (uint32_t)(r * 128 + ((q ^ (r & 7)) * 16)), s + (size_t)r * ld * 2 + q * 16);
    }
}

__global__ __launch_bounds__(256) void gemm_bf(
    const __nv_bfloat16* __restrict__ Ah, const __nv_bfloat16* __restrict__ Al,
    long long lda, long long sAb,
    const __nv_bfloat16* __restrict__ Bh, const __nv_bfloat16* __restrict__ Bl,
    long long ldb, long long sBb,
    float* __restrict__ Cm, long long ldc, long long sCb,
    int K,
    const float* __restrict__ bias_n, const float* __restrict__ bias_m,
    const float* __restrict__ res, long long ldr, long long sRb,
    float alpha)
{
    extern __shared__ char dsm[];
    char* base = (char*)((((uintptr_t)dsm) + 1023) & ~(uintptr_t)1023);
    const uint32_t sbase = smem_u32(base);
    const int tid = threadIdx.x, lane = tid & 31, wid = tid >> 5;

    int bb = blockIdx.z;
    Ah += (size_t)bb * sAb; Al += (size_t)bb * sAb;
    Bh += (size_t)bb * sBb; Bl += (size_t)bb * sBb;
    Cm += (size_t)bb * sCb;
    if (res) res += (size_t)bb * sRb;

    const int m0 = blockIdx.y * 128, n0 = blockIdx.x * 128;

    const int warp_m = (wid >> 1) * 32;
    const int warp_n = (wid & 1) * 64;
    const int lr = (lane & 7) + 8 * ((lane >> 3) & 1);
    const int lc = 16 * (lane >> 4);
    const uint32_t rA0 = (uint32_t)(warp_m + lr) * 128u;
    const uint32_t rA1 = (uint32_t)(warp_m + 16 + lr) * 128u;
    const uint32_t rB0 = (uint32_t)(warp_n + lr) * 128u;
    const uint32_t rB1 = (uint32_t)(warp_n + 16 + lr) * 128u;
    const uint32_t rB2 = (uint32_t)(warp_n + 32 + lr) * 128u;
    const uint32_t rB3 = (uint32_t)(warp_n + 48 + lr) * 128u;

    float acc[2][8][4] = {};

    // chunk 0 -> buf 0
    ld_plane(sbase,          Ah, lda, m0, 0, tid);
    ld_plane(sbase + 16384u, Al, lda, m0, 0, tid);
    ld_plane(sbase + 32768u, Bh, ldb, n0, 0, tid);
    ld_plane(sbase + 49152u, Bl, ldb, n0, 0, tid);
    CPCOMMIT();

    const int nk = K / 64;
    for (int i = 0; i < nk; i++) {
        if (i + 1 < nk) {
            uint32_t nb = sbase + (uint32_t)((i + 1) & 1) * 65536u;
            int k0 = (i + 1) * 64;
            ld_plane(nb,          Ah, lda, m0, k0, tid);
            ld_plane(nb + 16384u, Al, lda, m0, k0, tid);
            ld_plane(nb + 32768u, Bh, ldb, n0, k0, tid);
            ld_plane(nb + 49152u, Bl, ldb, n0, k0, tid);
        }
        CPCOMMIT();
        CPWAIT1();
        __syncthreads();

        uint32_t bufA = sbase + (uint32_t)(i & 1) * 65536u;
        uint32_t bufB = bufA + 32768u;
#pragma unroll
        for (int kk = 0; kk < 4; kk++) {
            uint32_t kof = 32u * kk + lc;
            uint32_t ah0[4], ah1[4], al0[4], al1[4];
            ldsm4(ah0, bufA + sw128(rA0 + kof));
            ldsm4(ah1, bufA + sw128(rA1 + kof));
            ldsm4(al0, bufA + 16384u + sw128(rA0 + kof));
            ldsm4(al1, bufA + 16384u + sw128(rA1 + kof));
            uint32_t bh[4][4], bl[4][4];
            ldsm4(bh[0], bufB + sw128(rB0 + kof));
            ldsm4(bh[1], bufB + sw128(rB1 + kof));
            ldsm4(bh[2], bufB + sw128(rB2 + kof));
            ldsm4(bh[3], bufB + sw128(rB3 + kof));
            ldsm4(bl[0], bufB + 16384u + sw128(rB0 + kof));
            ldsm4(bl[1], bufB + 16384u + sw128(rB1 + kof));
            ldsm4(bl[2], bufB + 16384u + sw128(rB2 + kof));
            ldsm4(bl[3], bufB + 16384u + sw128(rB3 + kof));
#pragma unroll
            for (int j = 0; j < 8; j++) {
                int nt2 = j >> 1, t = j & 1;
                uint32_t b0 = bh[nt2][t], b1 = bh[nt2][t + 2];
                uint32_t c0 = bl[nt2][t], c1 = bl[nt2][t + 2];
                mma16816(acc[0][j], ah0, b0, b1);
                mma16816(acc[1][j], ah1, b0, b1);
                mma16816(acc[0][j], al0, b0, b1);
                mma16816(acc[1][j], al1, b0, b1);
                mma16816(acc[0][j], ah0, c0, c1);
                mma16816(acc[1][j], ah1, c0, c1);
            }
        }
        __syncthreads();
    }

    const int er = lane >> 2, ec = (lane & 3) * 2;
#pragma unroll
    for (int mt = 0; mt < 2; mt++) {
#pragma unroll
        for (int half = 0; half < 2; half++) {
            int m = m0 + warp_m + mt * 16 + er + half * 8;
            float bm_ = bias_m ? bias_m[m] : 0.f;
#pragma unroll
            for (int j = 0; j < 8; j++) {
                int n = n0 + warp_n + j * 8 + ec;
                float v0 = alpha * acc[mt][j][half * 2 + 0] + bm_;
                float v1 = alpha * acc[mt][j][half * 2 + 1] + bm_;
                if (bias_n) { v0 += bias_n[n]; v1 += bias_n[n + 1]; }
                if (res) { const float* rp = res + (size_t)m * ldr + n; v0 += rp[0]; v1 += rp[1]; }
                *(float2*)&Cm[(size_t)m * ldc + n] = make_float2(v0, v1);
            }
        }
    }
}

// ---------------- GroupNorm -> transposed bf16 hi/lo planes [b][n][c] ----------------
__global__ __launch_bounds__(256) void gn_t_kernel(
    const float* __restrict__ x, const float* __restrict__ gamma,
    const float* __restrict__ beta,
    __nv_bfloat16* __restrict__ xnh, __nv_bfloat16* __restrict__ xnl)
{
    const int CG = C / NG;
    const int GE = CG * NSP;
    int b = blockIdx.x / NG, g = blockIdx.x % NG;
    const float* xp = x + ((size_t)b * C + (size_t)g * CG) * NSP;
    int t = threadIdx.x;

    float s = 0.f, s2 = 0.f;
    for (int i = t; i < GE; i += 256) { float v = xp[i]; s += v; s2 += v * v; }
    __shared__ float rs[256], rs2[256];
    rs[t] = s; rs2[t] = s2;
    __syncthreads();
    for (int st = 128; st > 0; st >>= 1) {
        if (t < st) { rs[t] += rs[t + st]; rs2[t] += rs2[t + st]; }
        __syncthreads();
    }
    float mu  = rs[0] * (1.f / GE);
    float var = rs2[0] * (1.f / GE) - mu * mu;
    float inv = rsqrtf(var + 1e-5f);

    __shared__ float tile[8][32][33];
    int warp = t >> 5, lane = t & 31;
    for (int tt = warp; tt < 64; tt += 8) {
        int ci = tt >> 5, ni = tt & 31;
        for (int i = 0; i < 32; i++) {
            int c = ci * 32 + i;
            int cg2 = g * CG + c;
            float v = xp[(size_t)c * NSP + ni * 32 + lane];
            tile[warp][i][lane] = (v - mu) * inv * gamma[cg2] + beta[cg2];
        }
        __syncwarp();
        for (int i = 0; i < 32; i++) {
            int n = ni * 32 + i;
            size_t off = ((size_t)b * NSP + n) * C + g * CG + ci * 32 + lane;
            float v = tile[warp][lane][i];
            __nv_bfloat16 h = __float2bfloat16(v);
            xnh[off] = h;
            xnl[off] = __float2bfloat16(v - __bfloat162float(h));
        }
        __syncwarp();
    }
}

// ---------------- K convert: qkvT[+C] fp32 -> tiled bf16 hi/lo planes ----------------
__global__ __launch_bounds__(256) void khl_kernel(const float* __restrict__ qkvT,
                                                  __nv_bfloat16* __restrict__ Kh,
                                                  __nv_bfloat16* __restrict__ Kl)
{
    int zz = blockIdx.x;
    int bh = zz >> 3, mc = zz & 7;
    int b = bh >> 2, h = bh & 3;
    const float* src = qkvT + ((size_t)b * NSP + mc * 128) * (3 * C) + C + h * DH;
    __nv_bfloat16* dh = Kh + (size_t)zz * 16384;
    __nv_bfloat16* dl = Kl + (size_t)zz * 16384;
    for (int idx = threadIdx.x; idx < 4096; idx += 256) {
        int r = idx >> 5, c4 = idx & 31;
        float4 v = *(const float4*)(src + (size_t)r * (3 * C) + c4 * 4);
        int d0 = c4 * 4, p = d0 >> 6, cc = d0 & 63;
        int o = p * 8192 + r * 64 + cc;
        __nv_bfloat16 h0 = __float2bfloat16(v.x), h1 = __float2bfloat16(v.y);
        __nv_bfloat16 h2 = __float2bfloat16(v.z), h3 = __float2bfloat16(v.w);
        dh[o] = h0; dh[o+1] = h1; dh[o+2] = h2; dh[o+3] = h3;
        dl[o]   = __float2bfloat16(v.x - __bfloat162float(h0));
        dl[o+1] = __float2bfloat16(v.y - __bfloat162float(h1));
        dl[o+2] = __float2bfloat16(v.z - __bfloat162float(h2));
        dl[o+3] = __float2bfloat16(v.w - __bfloat162float(h3));
    }
}

// ---------------- V convert+transpose: qkvT[+2C] -> Vh/Vl [bh][chunk][2 p][128 d][64 kv] ----------------
__global__ __launch_bounds__(256) void vhl_kernel(const float* __restrict__ qkvT,
                                                  __nv_bfloat16* __restrict__ Vh,
                                                  __nv_bfloat16* __restrict__ Vl)
{
    extern __shared__ float vt[];   // [128][129]
    int zz = blockIdx.x;
    int bh = zz >> 3, mc = zz & 7;
    int b = bh >> 2, h = bh & 3;
    const float* src = qkvT + ((size_t)b * NSP + mc * 128) * (3 * C) + 2 * C + h * DH;
    for (int idx = threadIdx.x; idx < 4096; idx += 256) {
        int r = idx >> 5, c4 = idx & 31;
        float4 v = *(const float4*)(src + (size_t)r * (3 * C) + c4 * 4);
        float* tp = vt + r * 129 + c4 * 4;
        tp[0] = v.x; tp[1] = v.y; tp[2] = v.z; tp[3] = v.w;
    }
    __syncthreads();
    __nv_bfloat16* dh = Vh + (size_t)zz * 16384;
    __nv_bfloat16* dl = Vl + (size_t)zz * 16384;
    for (int idx = threadIdx.x; idx < 8192; idx += 256) {
        int o2 = idx * 2;
        int p = o2 >> 13, rem = o2 & 8191;
        int d = rem >> 6, kvc = rem & 63;
        float v0 = vt[(p * 64 + kvc) * 129 + d];
        float v1 = vt[(p * 64 + kvc + 1) * 129 + d];
        __nv_bfloat16 h0 = __float2bfloat16(v0), h1 = __float2bfloat16(v1);
        dh[o2] = h0; dh[o2 + 1] = h1;
        dl[o2]     = __float2bfloat16(v0 - __bfloat162float(h0));
        dl[o2 + 1] = __float2bfloat16(v1 - __bfloat162float(h1));
    }
}

// ---------------- fused flash attention ----------------
#define FSM_Q 0
#define FSM_K 65536
#define FSM_V 131072

__device__ __forceinline__ void load_kv_tile(uint32_t sdst,
    const __nv_bfloat16* __restrict__ hp, const __nv_bfloat16* __restrict__ lp,
    int chunk, int tid)
{
    const char* srcH = (const char*)(hp + (size_t)chunk * 16384);
    const char* srcL = (const char*)(lp + (size_t)chunk * 16384);
#pragma unroll
    for (int p = 0; p < 2; p++) {
#pragma unroll
        for (int wv = 0; wv < 4; wv++) {
            int idx = tid + wv * 256;
            int r = idx >> 3, q = idx & 7;
            uint32_t d = sdst + p * 16384 + r * 128 + ((q ^ (r & 7)) * 16);
            CPA16(d,         srcH + p * 16384 + idx * 16);
            CPA16(d + 32768, srcL + p * 16384 + idx * 16);
        }
    }
}

__global__ __launch_bounds__(256) void flash_kernel(
    const float* __restrict__ qkvT,
    const __nv_bfloat16* __restrict__ Kh, const __nv_bfloat16* __restrict__ Kl,
    const __nv_bfloat16* __restrict__ Vh, const __nv_bfloat16* __restrict__ Vl,
    __nv_bfloat16* __restrict__ atth, __nv_bfloat16* __restrict__ attl)
{
    extern __shared__ char dsm[];
    char* base = (char*)((((uintptr_t)dsm) + 1023) & ~(uintptr_t)1023);
    const uint32_t sb = smem_u32(base);
    const int tid = threadIdx.x, lane = tid & 31, wid = tid >> 5;
    const int qb = blockIdx.x;
    const int z = blockIdx.y;
    const int b = z >> 2, h = z & 3;

    const __nv_bfloat16* KhP = Kh + (size_t)z * 8 * 16384;
    const __nv_bfloat16* KlP = Kl + (size_t)z * 8 * 16384;
    const __nv_bfloat16* VhP = Vh + (size_t)z * 8 * 16384;
    const __nv_bfloat16* VlP = Vl + (size_t)z * 8 * 16384;

    load_kv_tile(sb + FSM_K, KhP, KlP, 0, tid); CPCOMMIT();
    load_kv_tile(sb + FSM_V, VhP, VlP, 0, tid); CPCOMMIT();

    // Q prologue: fp32 -> bf16 hi/lo smem panels, scale*log2e folded
    {
        const float* Qg = qkvT + ((size_t)b * NSP + qb * 128) * (3 * C) + h * DH;
        int r = tid >> 1, hc = (tid & 1) * 64;
#pragma unroll
        for (int q4 = 0; q4 < 16; q4++) {
            int d0 = hc + q4 * 4;
            float4 v = *(const float4*)(Qg + (size_t)r * (3 * C) + d0);
            v.x *= SC2; v.y *= SC2; v.z *= SC2; v.w *= SC2;
            int p = d0 >> 6, cc = d0 & 63;
            uint32_t swoff = (uint32_t)r * 128u + ((uint32_t)(cc * 2) ^ ((r & 7) * 16));
            sts_hl(base + FSM_Q + p * 16384, swoff, v);
        }
    }
    __syncthreads();

    const int lr = (lane & 7) + 8 * ((lane >> 3) & 1);
    const uint32_t lc = 16u * (lane >> 4);
    const uint32_t qrow = 16u * wid + lr;
    const uint32_t qoff = qrow * 128u;
    const uint32_t qxor = (qrow & 7) * 16u;

    float accO[16][4] = {};
    float M0 = -1e30f, M1 = -1e30f, L0 = 0.f, L1 = 0.f;

    for (int c = 0; c < 8; c++) {
        float accS[16][4] = {};
        CPWAIT1(); __syncthreads();
        // ---- QK ----
#pragma unroll
        for (int p = 0; p < 2; p++) {
#pragma unroll
            for (int kk = 0; kk < 4; kk++) {
                uint32_t kof = 32u * kk + lc;
                uint32_t qa = sb + FSM_Q + p * 16384 + qoff + (kof ^ qxor);
                uint32_t ah[4], al[4];
                ldsm4(ah, qa); ldsm4(al, qa + 32768);
#pragma unroll
                for (int nt = 0; nt < 8; nt++) {
                    uint32_t krow = nt * 16 + lr;
                    uint32_t ka = sb + FSM_K + p * 16384 + krow * 128 + (kof ^ ((krow & 7) * 16));
                    uint32_t bh_[4], bl_[4];
                    ldsm4(bh_, ka); ldsm4(bl_, ka + 32768);
                    mma16816(accS[2*nt],   ah, bh_[0], bh_[2]);
                    mma16816(accS[2*nt],   al, bh_[0], bh_[2]);
                    mma16816(accS[2*nt],   ah, bl_[0], bl_[2]);
                    mma16816(accS[2*nt+1], ah, bh_[1], bh_[3]);
                    mma16816(accS[2*nt+1], al, bh_[1], bh_[3]);
                    mma16816(accS[2*nt+1], ah, bl_[1], bl_[3]);
                }
            }
        }
        __syncthreads();
        if (c + 1 < 8) load_kv_tile(sb + FSM_K, KhP, KlP, c + 1, tid);
        CPCOMMIT();
        // ---- online softmax (base-2) ----
        float m0 = -1e30f, m1 = -1e30f;
#pragma unroll
        for (int j = 0; j < 16; j++) {
            m0 = fmaxf(m0, fmaxf(accS[j][0], accS[j][1]));
            m1 = fmaxf(m1, fmaxf(accS[j][2], accS[j][3]));
        }
        m0 = fmaxf(m0, __shfl_xor_sync(0xffffffffu, m0, 1));
        m0 = fmaxf(m0, __shfl_xor_sync(0xffffffffu, m0, 2));
        m1 = fmaxf(m1, __shfl_xor_sync(0xffffffffu, m1, 1));
        m1 = fmaxf(m1, __shfl_xor_sync(0xffffffffu, m1, 2));
        float nM0 = fmaxf(M0, m0), nM1 = fmaxf(M1, m1);
        float a0 = exp2f(M0 - nM0), a1 = exp2f(M1 - nM1);
        M0 = nM0; M1 = nM1;
        float s0 = 0.f, s1 = 0.f;
#pragma unroll
        for (int j = 0; j < 16; j++) {
            accS[j][0] = exp2f(accS[j][0] - M0);
            accS[j][1] = exp2f(accS[j][1] - M0);
            accS[j][2] = exp2f(accS[j][2] - M1);
            accS[j][3] = exp2f(accS[j][3] - M1);
            s0 += accS[j][0] + accS[j][1];
            s1 += accS[j][2] + accS[j][3];
        }
        s0 += __shfl_xor_sync(0xffffffffu, s0, 1);
        s0 += __shfl_xor_sync(0xffffffffu, s0, 2);
        s1 += __shfl_xor_sync(0xffffffffu, s1, 1);
        s1 += __shfl_xor_sync(0xffffffffu, s1, 2);
        L0 = L0 * a0 + s0;
        L1 = L1 * a1 + s1;
#pragma unroll
        for (int j = 0; j < 16; j++) {
            accO[j][0] *= a0; accO[j][1] *= a0;
            accO[j][2] *= a1; accO[j][3] *= a1;
        }
        CPWAIT1(); __syncthreads();
        // ---- PV ----
#pragma unroll
        for (int p = 0; p < 2; p++) {
#pragma unroll
            for (int kk = 0; kk < 4; kk++) {
                int kt = p * 4 + kk;
                uint32_t kof = 32u * kk + lc;
                uint32_t phi[4], plo[4];
                {
                    const float* e0 = accS[2*kt];
                    const float* e1 = accS[2*kt+1];
                    phi[0] = pk2(e0[0], e0[1]);
                    phi[1] = pk2(e0[2], e0[3]);
                    phi[2] = pk2(e1[0], e1[1]);
                    phi[3] = pk2(e1[2], e1[3]);
                    plo[0] = pk2(e0[0] - lo16f(phi[0]), e0[1] - hi16f(phi[0]));
                    plo[1] = pk2(e0[2] - lo16f(phi[1]), e0[3] - hi16f(phi[1]));
                    plo[2] = pk2(e1[0] - lo16f(phi[2]), e1[1] - hi16f(phi[2]));
                    plo[3] = pk2(e1[2] - lo16f(phi[3]), e1[3] - hi16f(phi[3]));
                }
#pragma unroll
                for (int nt = 0; nt < 8; nt++) {
                    uint32_t vrow = nt * 16 + lr;
                    uint32_t va = sb + FSM_V + p * 16384 + vrow * 128 + (kof ^ ((vrow & 7) * 16));
                    uint32_t vh_[4], vl_[4];
                    ldsm4(vh_, va); ldsm4(vl_, va + 32768);
                    mma16816(accO[2*nt],   phi, vh_[0], vh_[2]);
                    mma16816(accO[2*nt],   plo, vh_[0], vh_[2]);
                    mma16816(accO[2*nt],   phi, vl_[0], vl_[2]);
                    mma16816(accO[2*nt+1], phi, vh_[1], vh_[3]);
                    mma16816(accO[2*nt+1], plo, vh_[1], vh_[3]);
                    mma16816(accO[2*nt+1], phi, vl_[1], vl_[3]);
                }
            }
        }
        __syncthreads();
        if (c + 1 < 8) load_kv_tile(sb + FSM_V, VhP, VlP, c + 1, tid);
        CPCOMMIT();
    }

    // epilogue -> bf16 hi/lo att planes
    float i0 = 1.f / L0, i1 = 1.f / L1;
    int row0 = qb * 128 + 16 * wid + (lane >> 2);
    int ec = (lane & 3) * 2;
    size_t base_off = ((size_t)b * NSP + row0) * C + h * DH;
#pragma unroll
    for (int j = 0; j < 16; j++) {
        int col = j * 8 + ec;
        {
            float o0 = accO[j][0] * i0, o1 = accO[j][1] * i0;
            uint32_t ph = pk2(o0, o1);
            uint32_t pl = pk2(o0 - lo16f(ph), o1 - hi16f(ph));
            *(uint32_t*)(atth + base_off + col) = ph;
            *(uint32_t*)(attl + base_off + col) = pl;
        }
        {
            float o0 = accO[j][2] * i1, o1 = accO[j][3] * i1;
            uint32_t ph = pk2(o0, o1);
            uint32_t pl = pk2(o0 - lo16f(ph), o1 - hi16f(ph));
            *(uint32_t*)(atth + base_off + (size_t)8 * C + col) = ph;
            *(uint32_t*)(attl + base_off + (size_t)8 * C + col) = pl;
        }
    }
}

// ---------------- launch ----------------
extern "C" void kernel_launch(void* const* d_in, const int* in_sizes, int n_in,
                              void* d_out, int out_size)
{
    const float* x      = (const float*)d_in[0];
    const float* gamma  = (const float*)d_in[1];
    const float* beta   = (const float*)d_in[2];
    const float* qkv_w  = (const float*)d_in[3];
    const float* qkv_b  = (const float*)d_in[4];
    const float* proj_w = (const float*)d_in[5];
    const float* proj_b = (const float*)d_in[6];
    float* out = (float*)d_out;

    float* qkvT;
    __nv_bfloat16 *xnh, *xnl, *qwh, *qwl, *pwh, *pwl, *atth, *attl, *Kh, *Kl, *Vh, *Vl;
    cudaGetSymbolAddress((void**)&qkvT, g_qkvT);
    cudaGetSymbolAddress((void**)&xnh,  g_xnh);
    cudaGetSymbolAddress((void**)&xnl,  g_xnl);
    cudaGetSymbolAddress((void**)&qwh,  g_qwh);
    cudaGetSymbolAddress((void**)&qwl,  g_qwl);
    cudaGetSymbolAddress((void**)&pwh,  g_pwh);
    cudaGetSymbolAddress((void**)&pwl,  g_pwl);
    cudaGetSymbolAddress((void**)&atth, g_atth);
    cudaGetSymbolAddress((void**)&attl, g_attl);
    cudaGetSymbolAddress((void**)&Kh,   g_Kh);
    cudaGetSymbolAddress((void**)&Kl,   g_Kl);
    cudaGetSymbolAddress((void**)&Vh,   g_Vh);
    cudaGetSymbolAddress((void**)&Vl,   g_Vl);

    const int DSM  = 1024 + 2 * 65536;
    const int FDSM = 1024 + 3 * 65536;
    const int VDSM = 128 * 129 * 4;
    cudaFuncSetAttribute(gemm_bf,      cudaFuncAttributeMaxDynamicSharedMemorySize, DSM);
    cudaFuncSetAttribute(flash_kernel, cudaFuncAttributeMaxDynamicSharedMemorySize, FDSM);
    cudaFuncSetAttribute(vhl_kernel,   cudaFuncAttributeMaxDynamicSharedMemorySize, VDSM);

    // 0) weight planes
    wcvt_kernel<<<(3 * C * C + 255) / 256, 256>>>(qkv_w, qwh, qwl, 3 * C * C);
    wcvt_kernel<<<(C * C + 255) / 256, 256>>>(proj_w, pwh, pwl, C * C);

    // 1) GroupNorm -> xn planes
    gn_t_kernel<<<B * NG, 256>>>(x, gamma, beta, xnh, xnl);

    // 2) QKV GEMM: qkvT[b][n][o] = xn[n,:] @ qkv_w[o,:]^T + qkv_b
    gemm_bf<<<dim3(12, 8, B), 256, DSM>>>(
        xnh, xnl, C, (long long)NSP * C,
        qwh, qwl, C, 0,
        qkvT, 3 * C, (long long)NSP * 3 * C,
        C, qkv_b, nullptr, nullptr, 0, 0, 1.f);

    // 3) K/V plane conversion
    khl_kernel<<<B * NH * 8, 256>>>(qkvT, Kh, Kl);
    vhl_kernel<<<B * NH * 8, 256, VDSM>>>(qkvT, Vh, Vl);

    // 4) fused attention -> att planes [b][n][c]
    flash_kernel<<<dim3(8, B * NH), 256, FDSM>>>(qkvT, Kh, Kl, Vh, Vl, atth, attl);

    // 5) proj + bias + residual: out[b][c][n]
    gemm_bf<<<dim3(8, 4, B), 256, DSM>>>(
        pwh, pwl, C, 0,
        atth, attl, C, (long long)NSP * C,
        out, NSP, (long long)C * NSP,
        C, nullptr, proj_b, x, NSP, (long long)C * NSP, 1.f);
}

// round 6
// speedup vs baseline: 2.9224x; 1.0561x over previous
#include <cuda_runtime.h>
#include <cuda_bf16.h>
#include <math.h>
#include <stdint.h>

#define B   16
#define C   512
#define NSP 1024
#define NH  4
#define DH  128
#define NG  8
#define SC2 (0.08838834764831845f * 1.4426950408889634f)   // scale * log2(e)

// ---------------- scratch ----------------
__device__ __nv_bfloat16 g_xnh[(size_t)B*NSP*C];
__device__ __nv_bfloat16 g_xnl[(size_t)B*NSP*C];
__device__ __nv_bfloat16 g_qwh[(size_t)3*C*C];
__device__ __nv_bfloat16 g_qwl[(size_t)3*C*C];
__device__ __nv_bfloat16 g_pwh[(size_t)C*C];
__device__ __nv_bfloat16 g_pwl[(size_t)C*C];
__device__ __nv_bfloat16 g_Qh [(size_t)B*NSP*C];     // [b][n][c_q] scale folded
__device__ __nv_bfloat16 g_Ql [(size_t)B*NSP*C];
__device__ __nv_bfloat16 g_atth[(size_t)B*NSP*C];
__device__ __nv_bfloat16 g_attl[(size_t)B*NSP*C];
// K/V planes, tiled: [bh][8 chunks][2 panels][128 rows][64 cols]
__device__ __nv_bfloat16 g_Kh[(size_t)B*NH*NSP*DH];
__device__ __nv_bfloat16 g_Kl[(size_t)B*NH*NSP*DH];
__device__ __nv_bfloat16 g_Vh[(size_t)B*NH*NSP*DH];
__device__ __nv_bfloat16 g_Vl[(size_t)B*NH*NSP*DH];

// ---------------- helpers ----------------
__device__ __forceinline__ uint32_t smem_u32(const void* p) {
    uint32_t a;
    asm("{ .reg .u64 t; cvta.to.shared.u64 t, %1; cvt.u32.u64 %0, t; }" : "=r"(a) : "l"(p));
    return a;
}
__device__ __forceinline__ void ldsm4(uint32_t* r, uint32_t a) {
    asm volatile("ldmatrix.sync.aligned.m8n8.x4.shared.b16 {%0,%1,%2,%3}, [%4];"
        : "=r"(r[0]), "=r"(r[1]), "=r"(r[2]), "=r"(r[3]) : "r"(a));
}
__device__ __forceinline__ void mma16816(float* d, const uint32_t* a, uint32_t b0, uint32_t b1) {
    asm volatile("mma.sync.aligned.m16n8k16.row.col.f32.bf16.bf16.f32 "
        "{%0,%1,%2,%3}, {%4,%5,%6,%7}, {%8,%9}, {%0,%1,%2,%3};"
        : "+f"(d[0]), "+f"(d[1]), "+f"(d[2]), "+f"(d[3])
        : "r"(a[0]), "r"(a[1]), "r"(a[2]), "r"(a[3]), "r"(b0), "r"(b1));
}
__device__ __forceinline__ uint32_t pk2(float lo, float hi) {
    uint32_t r;
    asm("cvt.rn.bf16x2.f32 %0, %1, %2;" : "=r"(r) : "f"(hi), "f"(lo));
    return r;
}
__device__ __forceinline__ float lo16f(uint32_t u) { return __uint_as_float(u << 16); }
__device__ __forceinline__ float hi16f(uint32_t u) { return __uint_as_float(u & 0xFFFF0000u); }

#define CPA16(dst, src) asm volatile("cp.async.cg.shared.global [%0], [%1], 16;" :: "r"(dst), "l"(src))
#define CPCOMMIT() asm volatile("cp.async.commit_group;" ::: "memory")
#define CPWAIT1()  asm volatile("cp.async.wait_group 1;" ::: "memory")

// ---------------- weight convert ----------------
__global__ __launch_bounds__(256) void wcvt_kernel(const float* __restrict__ src,
    __nv_bfloat16* __restrict__ dh, __nv_bfloat16* __restrict__ dl, int n)
{
    int i = blockIdx.x * 256 + threadIdx.x;
    if (i < n) {
        float v = src[i];
        __nv_bfloat16 h = __float2bfloat16(v);
        dh[i] = h;
        dl[i] = __float2bfloat16(v - __bfloat162float(h));
    }
}

// ---------------- shared GEMM mainloop ----------------
// 128x128 tile, A/B bf16 hi/lo planes, cp.async double-buffered, acc[2][8][4].
__device__ __forceinline__ void ld_plane(uint32_t sdst, const __nv_bfloat16* __restrict__ src,
                                         long long ld, int row0, int k0, int tid)
{
    const char* s = (const char*)src + ((size_t)row0 * ld + k0) * 2;
#pragma unroll
    for (int g = 0; g < 4; g++) {
        int idx = tid + g * 256;
        int r = idx >> 3, q = idx & 7;
        CPA16(sdst + (uint32_t)(r * 128 + ((q ^ (r & 7)) * 16)), s + (size_t)r * ld * 2 + q * 16);
    }
}

__device__ __forceinline__ void gemm_mainloop(uint32_t sbase,
    const __nv_bfloat16* __restrict__ Ah, const __nv_bfloat16* __restrict__ Al,
    long long lda, int m0,
    const __nv_bfloat16* __restrict__ Bh, const __nv_bfloat16* __restrict__ Bl,
    long long ldb, int n0,
    int K, float (&acc)[2][8][4])
{
    const int tid = threadIdx.x, lane = tid & 31, wid = tid >> 5;
    const int warp_m = (wid >> 1) * 32;
    const int warp_n = (wid & 1) * 64;
    const int lr = (lane & 7) + 8 * ((lane >> 3) & 1);
    const int lc = 16 * (lane >> 4);
    const uint32_t rx = (uint32_t)(lr & 7) * 16u;
    uint32_t kx[4];
#pragma unroll
    for (int k = 0; k < 4; k++)
        kx[k] = ((32u * k) ^ (rx & 0x60u)) + ((uint32_t)lc ^ (rx & 0x10u));

    const uint32_t rA0 = (uint32_t)(warp_m + lr) * 128u;
    const uint32_t rA1 = rA0 + 16u * 128u;
    const uint32_t rB0 = (uint32_t)(warp_n + lr) * 128u;
    const uint32_t rB1 = rB0 + 16u * 128u;
    const uint32_t rB2 = rB0 + 32u * 128u;
    const uint32_t rB3 = rB0 + 48u * 128u;

    ld_plane(sbase,          Ah, lda, m0, 0, tid);
    ld_plane(sbase + 16384u, Al, lda, m0, 0, tid);
    ld_plane(sbase + 32768u, Bh, ldb, n0, 0, tid);
    ld_plane(sbase + 49152u, Bl, ldb, n0, 0, tid);
    CPCOMMIT();

    const int nk = K / 64;
    for (int i = 0; i < nk; i++) {
        if (i + 1 < nk) {
            uint32_t nb2 = sbase + (uint32_t)((i + 1) & 1) * 65536u;
            int k0 = (i + 1) * 64;
            ld_plane(nb2,          Ah, lda, m0, k0, tid);
            ld_plane(nb2 + 16384u, Al, lda, m0, k0, tid);
            ld_plane(nb2 + 32768u, Bh, ldb, n0, k0, tid);
            ld_plane(nb2 + 49152u, Bl, ldb, n0, k0, tid);
        }
        CPCOMMIT();
        CPWAIT1();
        __syncthreads();

        uint32_t bufA = sbase + (uint32_t)(i & 1) * 65536u;
        uint32_t bufB = bufA + 32768u;
#pragma unroll
        for (int kk = 0; kk < 4; kk++) {
            uint32_t kof = kx[kk];
            uint32_t ah0[4], ah1[4], al0[4], al1[4];
            ldsm4(ah0, bufA + rA0 + kof);
            ldsm4(ah1, bufA + rA1 + kof);
            ldsm4(al0, bufA + 16384u + rA0 + kof);
            ldsm4(al1, bufA + 16384u + rA1 + kof);
            uint32_t bh[4][4], bl[4][4];
            ldsm4(bh[0], bufB + rB0 + kof);
            ldsm4(bh[1], bufB + rB1 + kof);
            ldsm4(bh[2], bufB + rB2 + kof);
            ldsm4(bh[3], bufB + rB3 + kof);
            ldsm4(bl[0], bufB + 16384u + rB0 + kof);
            ldsm4(bl[1], bufB + 16384u + rB1 + kof);
            ldsm4(bl[2], bufB + 16384u + rB2 + kof);
            ldsm4(bl[3], bufB + 16384u + rB3 + kof);
#pragma unroll
            for (int j = 0; j < 8; j++) {
                int nt2 = j >> 1, t = j & 1;
                uint32_t b0 = bh[nt2][t], b1 = bh[nt2][t + 2];
                uint32_t c0 = bl[nt2][t], c1 = bl[nt2][t + 2];
                mma16816(acc[0][j], ah0, b0, b1);
                mma16816(acc[1][j], ah1, b0, b1);
                mma16816(acc[0][j], al0, b0, b1);
                mma16816(acc[1][j], al1, b0, b1);
                mma16816(acc[0][j], ah0, c0, c1);
                mma16816(acc[1][j], ah1, c0, c1);
            }
        }
        __syncthreads();
    }
}

// ---------------- QKV GEMM with fused Q/K/V-plane epilogues ----------------
// grid (12, 8, B): x = output channel block (0-3 Q, 4-7 K, 8-11 V), y = spatial block.
__global__ __launch_bounds__(256) void gemm_qkv(
    const __nv_bfloat16* __restrict__ xnh, const __nv_bfloat16* __restrict__ xnl,
    const __nv_bfloat16* __restrict__ qwh, const __nv_bfloat16* __restrict__ qwl,
    const float* __restrict__ bias,
    __nv_bfloat16* __restrict__ Qh, __nv_bfloat16* __restrict__ Ql,
    __nv_bfloat16* __restrict__ Kh, __nv_bfloat16* __restrict__ Kl,
    __nv_bfloat16* __restrict__ Vh, __nv_bfloat16* __restrict__ Vl)
{
    extern __shared__ char dsm[];
    char* base = (char*)((((uintptr_t)dsm) + 1023) & ~(uintptr_t)1023);
    const uint32_t sbase = smem_u32(base);
    const int tid = threadIdx.x, lane = tid & 31, wid = tid >> 5;
    const int bb = blockIdx.z;
    const int nb = blockIdx.x;
    const int m0 = blockIdx.y * 128, n0 = nb * 128;

    float acc[2][8][4] = {};
    gemm_mainloop(sbase,
        xnh + (size_t)bb * NSP * C, xnl + (size_t)bb * NSP * C, C, m0,
        qwh, qwl, C, n0, C, acc);

    const int warp_m = (wid >> 1) * 32;
    const int warp_n = (wid & 1) * 64;
    const int er = lane >> 2, ec = (lane & 3) * 2;

    if (nb < 4) {
        // Q planes, scale folded
#pragma unroll
        for (int mt = 0; mt < 2; mt++)
#pragma unroll
        for (int half = 0; half < 2; half++) {
            int m = m0 + warp_m + mt * 16 + er + half * 8;
            __nv_bfloat16* qh = Qh + ((size_t)bb * NSP + m) * C;
            __nv_bfloat16* ql = Ql + ((size_t)bb * NSP + m) * C;
#pragma unroll
            for (int j = 0; j < 8; j++) {
                int n = n0 + warp_n + j * 8 + ec;
                float v0 = (acc[mt][j][half * 2 + 0] + bias[n])     * SC2;
                float v1 = (acc[mt][j][half * 2 + 1] + bias[n + 1]) * SC2;
                uint32_t ph = pk2(v0, v1);
                uint32_t pl = pk2(v0 - lo16f(ph), v1 - hi16f(ph));
                *(uint32_t*)(qh + n) = ph;
                *(uint32_t*)(ql + n) = pl;
            }
        }
    } else if (nb < 8) {
        // K tiled planes
        int h = nb - 4, mc = m0 >> 7;
        size_t po = ((size_t)(bb * NH + h) * 8 + mc) * 16384;
        __nv_bfloat16* dh = Kh + po;
        __nv_bfloat16* dl = Kl + po;
#pragma unroll
        for (int mt = 0; mt < 2; mt++)
#pragma unroll
        for (int half = 0; half < 2; half++) {
            int mloc = warp_m + mt * 16 + er + half * 8;
#pragma unroll
            for (int j = 0; j < 8; j++) {
                int dloc = warp_n + j * 8 + ec;
                int n = n0 + dloc;
                float v0 = acc[mt][j][half * 2 + 0] + bias[n];
                float v1 = acc[mt][j][half * 2 + 1] + bias[n + 1];
                uint32_t ph = pk2(v0, v1);
                uint32_t pl = pk2(v0 - lo16f(ph), v1 - hi16f(ph));
                int o = ((dloc >> 6) << 13) + mloc * 64 + (dloc & 63);
                *(uint32_t*)(dh + o) = ph;
                *(uint32_t*)(dl + o) = pl;
            }
        }
    } else {
        // V: stage via smem transpose, then tiled planes
        int h = nb - 8, mc = m0 >> 7;
        float* vt = (float*)base;   // [128][129]
#pragma unroll
        for (int mt = 0; mt < 2; mt++)
#pragma unroll
        for (int half = 0; half < 2; half++) {
            int mloc = warp_m + mt * 16 + er + half * 8;
#pragma unroll
            for (int j = 0; j < 8; j++) {
                int dloc = warp_n + j * 8 + ec;
                int n = n0 + dloc;
                vt[mloc * 129 + dloc]     = acc[mt][j][half * 2 + 0] + bias[n];
                vt[mloc * 129 + dloc + 1] = acc[mt][j][half * 2 + 1] + bias[n + 1];
            }
        }
        __syncthreads();
        size_t po = ((size_t)(bb * NH + h) * 8 + mc) * 16384;
        __nv_bfloat16* dh = Vh + po;
        __nv_bfloat16* dl = Vl + po;
        for (int idx = tid; idx < 8192; idx += 256) {
            int o2 = idx * 2;
            int p = o2 >> 13, rem = o2 & 8191;
            int d = rem >> 6, kvc = rem & 63;
            float v0 = vt[(p * 64 + kvc) * 129 + d];
            float v1 = vt[(p * 64 + kvc + 1) * 129 + d];
            uint32_t ph = pk2(v0, v1);
            uint32_t pl = pk2(v0 - lo16f(ph), v1 - hi16f(ph));
            *(uint32_t*)(dh + o2) = ph;
            *(uint32_t*)(dl + o2) = pl;
        }
    }
}

// ---------------- generic GEMM (proj): C[M,N] = A@B^T + bias_m + res ----------------
__global__ __launch_bounds__(256) void gemm_bf(
    const __nv_bfloat16* __restrict__ Ah, const __nv_bfloat16* __restrict__ Al,
    long long lda, long long sAb,
    const __nv_bfloat16* __restrict__ Bh, const __nv_bfloat16* __restrict__ Bl,
    long long ldb, long long sBb,
    float* __restrict__ Cm, long long ldc, long long sCb,
    int K,
    const float* __restrict__ bias_m,
    const float* __restrict__ res, long long ldr, long long sRb)
{
    extern __shared__ char dsm[];
    char* base = (char*)((((uintptr_t)dsm) + 1023) & ~(uintptr_t)1023);
    const uint32_t sbase = smem_u32(base);
    const int lane = threadIdx.x & 31, wid = threadIdx.x >> 5;
    const int bb = blockIdx.z;
    const int m0 = blockIdx.y * 128, n0 = blockIdx.x * 128;

    float acc[2][8][4] = {};
    gemm_mainloop(sbase,
        Ah + (size_t)bb * sAb, Al + (size_t)bb * sAb, lda, m0,
        Bh + (size_t)bb * sBb, Bl + (size_t)bb * sBb, ldb, n0, K, acc);

    Cm += (size_t)bb * sCb;
    if (res) res += (size_t)bb * sRb;
    const int warp_m = (wid >> 1) * 32, warp_n = (wid & 1) * 64;
    const int er = lane >> 2, ec = (lane & 3) * 2;
#pragma unroll
    for (int mt = 0; mt < 2; mt++)
#pragma unroll
    for (int half = 0; half < 2; half++) {
        int m = m0 + warp_m + mt * 16 + er + half * 8;
        float bm_ = bias_m ? bias_m[m] : 0.f;
#pragma unroll
        for (int j = 0; j < 8; j++) {
            int n = n0 + warp_n + j * 8 + ec;
            float v0 = acc[mt][j][half * 2 + 0] + bm_;
            float v1 = acc[mt][j][half * 2 + 1] + bm_;
            if (res) { const float* rp = res + (size_t)m * ldr + n; v0 += rp[0]; v1 += rp[1]; }
            *(float2*)&Cm[(size_t)m * ldc + n] = make_float2(v0, v1);
        }
    }
}

// ---------------- GroupNorm -> transposed bf16 hi/lo planes [b][n][c] ----------------
__global__ __launch_bounds__(256) void gn_t_kernel(
    const float* __restrict__ x, const float* __restrict__ gamma,
    const float* __restrict__ beta,
    __nv_bfloat16* __restrict__ xnh, __nv_bfloat16* __restrict__ xnl)
{
    const int CG = C / NG;
    const int GE = CG * NSP;
    int b = blockIdx.x / NG, g = blockIdx.x % NG;
    const float* xp = x + ((size_t)b * C + (size_t)g * CG) * NSP;
    int t = threadIdx.x;

    float s = 0.f, s2 = 0.f;
    for (int i = t; i < GE; i += 256) { float v = xp[i]; s += v; s2 += v * v; }
    __shared__ float rs[256], rs2[256];
    rs[t] = s; rs2[t] = s2;
    __syncthreads();
    for (int st = 128; st > 0; st >>= 1) {
        if (t < st) { rs[t] += rs[t + st]; rs2[t] += rs2[t + st]; }
        __syncthreads();
    }
    float mu  = rs[0] * (1.f / GE);
    float var = rs2[0] * (1.f / GE) - mu * mu;
    float inv = rsqrtf(var + 1e-5f);

    __shared__ float tile[8][32][33];
    int warp = t >> 5, lane = t & 31;
    for (int tt = warp; tt < 64; tt += 8) {
        int ci = tt >> 5, ni = tt & 31;
        for (int i = 0; i < 32; i++) {
            int c = ci * 32 + i;
            int cg2 = g * CG + c;
            float v = xp[(size_t)c * NSP + ni * 32 + lane];
            tile[warp][i][lane] = (v - mu) * inv * gamma[cg2] + beta[cg2];
        }
        __syncwarp();
        for (int i = 0; i < 32; i++) {
            int n = ni * 32 + i;
            size_t off = ((size_t)b * NSP + n) * C + g * CG + ci * 32 + lane;
            float v = tile[warp][lane][i];
            __nv_bfloat16 h = __float2bfloat16(v);
            xnh[off] = h;
            xnl[off] = __float2bfloat16(v - __bfloat162float(h));
        }
        __syncwarp();
    }
}

// ---------------- fused flash attention ----------------
#define FSM_Q 0
#define FSM_K 65536
#define FSM_V 131072

__device__ __forceinline__ void load_kv_tile(uint32_t sdst,
    const __nv_bfloat16* __restrict__ hp, const __nv_bfloat16* __restrict__ lp,
    int chunk, int tid)
{
    const char* srcH = (const char*)(hp + (size_t)chunk * 16384);
    const char* srcL = (const char*)(lp + (size_t)chunk * 16384);
#pragma unroll
    for (int p = 0; p < 2; p++) {
#pragma unroll
        for (int wv = 0; wv < 4; wv++) {
            int idx = tid + wv * 256;
            int r = idx >> 3, q = idx & 7;
            uint32_t d = sdst + p * 16384 + r * 128 + ((q ^ (r & 7)) * 16);
            CPA16(d,         srcH + p * 16384 + idx * 16);
            CPA16(d + 32768, srcL + p * 16384 + idx * 16);
        }
    }
}

__global__ __launch_bounds__(256) void flash_kernel(
    const __nv_bfloat16* __restrict__ Qh, const __nv_bfloat16* __restrict__ Ql,
    const __nv_bfloat16* __restrict__ Kh, const __nv_bfloat16* __restrict__ Kl,
    const __nv_bfloat16* __restrict__ Vh, const __nv_bfloat16* __restrict__ Vl,
    __nv_bfloat16* __restrict__ atth, __nv_bfloat16* __restrict__ attl)
{
    extern __shared__ char dsm[];
    char* base = (char*)((((uintptr_t)dsm) + 1023) & ~(uintptr_t)1023);
    const uint32_t sb = smem_u32(base);
    const int tid = threadIdx.x, lane = tid & 31, wid = tid >> 5;
    const int qb = blockIdx.x;
    const int z = blockIdx.y;
    const int b = z >> 2, h = z & 3;

    const __nv_bfloat16* KhP = Kh + (size_t)z * 8 * 16384;
    const __nv_bfloat16* KlP = Kl + (size_t)z * 8 * 16384;
    const __nv_bfloat16* VhP = Vh + (size_t)z * 8 * 16384;
    const __nv_bfloat16* VlP = Vl + (size_t)z * 8 * 16384;

    // Q via cp.async from pre-scaled planes (committed FIRST so wait_group 1 covers it)
    {
        const char* Qhp = (const char*)(Qh + ((size_t)b * NSP + qb * 128) * C + h * DH);
        const char* Qlp = (const char*)(Ql + ((size_t)b * NSP + qb * 128) * C + h * DH);
#pragma unroll
        for (int g = 0; g < 8; g++) {
            int idx = tid + g * 256;          // 0..2047
            int r = idx >> 4, q = idx & 15;
            uint32_t d = sb + FSM_Q + (q >> 3) * 16384 + r * 128 + (((q & 7) ^ (r & 7)) * 16);
            CPA16(d,         Qhp + (size_t)r * C * 2 + q * 16);
            CPA16(d + 32768, Qlp + (size_t)r * C * 2 + q * 16);
        }
    }
    CPCOMMIT();
    load_kv_tile(sb + FSM_K, KhP, KlP, 0, tid); CPCOMMIT();
    load_kv_tile(sb + FSM_V, VhP, VlP, 0, tid); CPCOMMIT();

    const int lr = (lane & 7) + 8 * ((lane >> 3) & 1);
    const int lc = 16 * (lane >> 4);
    const uint32_t rx = (uint32_t)(lr & 7) * 16u;
    uint32_t kx[4];
#pragma unroll
    for (int k = 0; k < 4; k++)
        kx[k] = ((32u * k) ^ (rx & 0x60u)) + ((uint32_t)lc ^ (rx & 0x10u));
    const uint32_t qoff = (uint32_t)(16 * wid + lr) * 128u;

    float accO[16][4] = {};
    float M0 = -1e30f, M1 = -1e30f, L0 = 0.f, L1 = 0.f;

    for (int c = 0; c < 8; c++) {
        float accS[16][4] = {};
        CPWAIT1(); __syncthreads();          // Q + K_c ready
        // ---- QK ----
#pragma unroll
        for (int p = 0; p < 2; p++) {
#pragma unroll
            for (int kk = 0; kk < 4; kk++) {
                uint32_t kof = kx[kk];
                uint32_t qa = sb + FSM_Q + p * 16384 + qoff + kof;
                uint32_t ah[4], al[4];
                ldsm4(ah, qa); ldsm4(al, qa + 32768);
#pragma unroll
                for (int nt = 0; nt < 8; nt++) {
                    uint32_t ka = sb + FSM_K + p * 16384 + (uint32_t)(nt * 16 + lr) * 128u + kof;
                    uint32_t bh_[4], bl_[4];
                    ldsm4(bh_, ka); ldsm4(bl_, ka + 32768);
                    mma16816(accS[2*nt],   ah, bh_[0], bh_[2]);
                    mma16816(accS[2*nt],   al, bh_[0], bh_[2]);
                    mma16816(accS[2*nt],   ah, bl_[0], bl_[2]);
                    mma16816(accS[2*nt+1], ah, bh_[1], bh_[3]);
                    mma16816(accS[2*nt+1], al, bh_[1], bh_[3]);
                    mma16816(accS[2*nt+1], ah, bl_[1], bl_[3]);
                }
            }
        }
        __syncthreads();
        if (c + 1 < 8) load_kv_tile(sb + FSM_K, KhP, KlP, c + 1, tid);
        CPCOMMIT();
        // ---- online softmax (base-2) ----
        float m0 = -1e30f, m1 = -1e30f;
#pragma unroll
        for (int j = 0; j < 16; j++) {
            m0 = fmaxf(m0, fmaxf(accS[j][0], accS[j][1]));
            m1 = fmaxf(m1, fmaxf(accS[j][2], accS[j][3]));
        }
        m0 = fmaxf(m0, __shfl_xor_sync(0xffffffffu, m0, 1));
        m0 = fmaxf(m0, __shfl_xor_sync(0xffffffffu, m0, 2));
        m1 = fmaxf(m1, __shfl_xor_sync(0xffffffffu, m1, 1));
        m1 = fmaxf(m1, __shfl_xor_sync(0xffffffffu, m1, 2));
        float nM0 = fmaxf(M0, m0), nM1 = fmaxf(M1, m1);
        float a0 = exp2f(M0 - nM0), a1 = exp2f(M1 - nM1);
        M0 = nM0; M1 = nM1;
        float s0 = 0.f, s1 = 0.f;
#pragma unroll
        for (int j = 0; j < 16; j++) {
            accS[j][0] = exp2f(accS[j][0] - M0);
            accS[j][1] = exp2f(accS[j][1] - M0);
            accS[j][2] = exp2f(accS[j][2] - M1);
            accS[j][3] = exp2f(accS[j][3] - M1);
            s0 += accS[j][0] + accS[j][1];
            s1 += accS[j][2] + accS[j][3];
        }
        s0 += __shfl_xor_sync(0xffffffffu, s0, 1);
        s0 += __shfl_xor_sync(0xffffffffu, s0, 2);
        s1 += __shfl_xor_sync(0xffffffffu, s1, 1);
        s1 += __shfl_xor_sync(0xffffffffu, s1, 2);
        L0 = L0 * a0 + s0;
        L1 = L1 * a1 + s1;
#pragma unroll
        for (int j = 0; j < 16; j++) {
            accO[j][0] *= a0; accO[j][1] *= a0;
            accO[j][2] *= a1; accO[j][3] *= a1;
        }
        CPWAIT1(); __syncthreads();          // V_c ready
        // ---- PV ----
#pragma unroll
        for (int p = 0; p < 2; p++) {
#pragma unroll
            for (int kk = 0; kk < 4; kk++) {
                int kt = p * 4 + kk;
                uint32_t kof = kx[kk];
                uint32_t phi[4], plo[4];
                {
                    const float* e0 = accS[2*kt];
                    const float* e1 = accS[2*kt+1];
                    phi[0] = pk2(e0[0], e0[1]);
                    phi[1] = pk2(e0[2], e0[3]);
                    phi[2] = pk2(e1[0], e1[1]);
                    phi[3] = pk2(e1[2], e1[3]);
                    plo[0] = pk2(e0[0] - lo16f(phi[0]), e0[1] - hi16f(phi[0]));
                    plo[1] = pk2(e0[2] - lo16f(phi[1]), e0[3] - hi16f(phi[1]));
                    plo[2] = pk2(e1[0] - lo16f(phi[2]), e1[1] - hi16f(phi[2]));
                    plo[3] = pk2(e1[2] - lo16f(phi[3]), e1[3] - hi16f(phi[3]));
                }
#pragma unroll
                for (int nt = 0; nt < 8; nt++) {
                    uint32_t va = sb + FSM_V + p * 16384 + (uint32_t)(nt * 16 + lr) * 128u + kof;
                    uint32_t vh_[4], vl_[4];
                    ldsm4(vh_, va); ldsm4(vl_, va + 32768);
                    mma16816(accO[2*nt],   phi, vh_[0], vh_[2]);
                    mma16816(accO[2*nt],   plo, vh_[0], vh_[2]);
                    mma16816(accO[2*nt],   phi, vl_[0], vl_[2]);
                    mma16816(accO[2*nt+1], phi, vh_[1], vh_[3]);
                    mma16816(accO[2*nt+1], plo, vh_[1], vh_[3]);
                    mma16816(accO[2*nt+1], phi, vl_[1], vl_[3]);
                }
            }
        }
        __syncthreads();
        if (c + 1 < 8) load_kv_tile(sb + FSM_V, VhP, VlP, c + 1, tid);
        CPCOMMIT();
    }

    // epilogue -> bf16 hi/lo att planes
    float i0 = 1.f / L0, i1 = 1.f / L1;
    int row0 = qb * 128 + 16 * wid + (lane >> 2);
    int ec = (lane & 3) * 2;
    size_t base_off = ((size_t)b * NSP + row0) * C + h * DH;
#pragma unroll
    for (int j = 0; j < 16; j++) {
        int col = j * 8 + ec;
        {
            float o0 = accO[j][0] * i0, o1 = accO[j][1] * i0;
            uint32_t ph = pk2(o0, o1);
            uint32_t pl = pk2(o0 - lo16f(ph), o1 - hi16f(ph));
            *(uint32_t*)(atth + base_off + col) = ph;
            *(uint32_t*)(attl + base_off + col) = pl;
        }
        {
            float o0 = accO[j][2] * i1, o1 = accO[j][3] * i1;
            uint32_t ph = pk2(o0, o1);
            uint32_t pl = pk2(o0 - lo16f(ph), o1 - hi16f(ph));
            *(uint32_t*)(atth + base_off + (size_t)8 * C + col) = ph;
            *(uint32_t*)(attl + base_off + (size_t)8 * C + col) = pl;
        }
    }
}

// ---------------- launch ----------------
extern "C" void kernel_launch(void* const* d_in, const int* in_sizes, int n_in,
                              void* d_out, int out_size)
{
    const float* x      = (const float*)d_in[0];
    const float* gamma  = (const float*)d_in[1];
    const float* beta   = (const float*)d_in[2];
    const float* qkv_w  = (const float*)d_in[3];
    const float* qkv_b  = (const float*)d_in[4];
    const float* proj_w = (const float*)d_in[5];
    const float* proj_b = (const float*)d_in[6];
    float* out = (float*)d_out;

    __nv_bfloat16 *xnh, *xnl, *qwh, *qwl, *pwh, *pwl, *Qh, *Ql, *atth, *attl, *Kh, *Kl, *Vh, *Vl;
    cudaGetSymbolAddress((void**)&xnh,  g_xnh);
    cudaGetSymbolAddress((void**)&xnl,  g_xnl);
    cudaGetSymbolAddress((void**)&qwh,  g_qwh);
    cudaGetSymbolAddress((void**)&qwl,  g_qwl);
    cudaGetSymbolAddress((void**)&pwh,  g_pwh);
    cudaGetSymbolAddress((void**)&pwl,  g_pwl);
    cudaGetSymbolAddress((void**)&Qh,   g_Qh);
    cudaGetSymbolAddress((void**)&Ql,   g_Ql);
    cudaGetSymbolAddress((void**)&atth, g_atth);
    cudaGetSymbolAddress((void**)&attl, g_attl);
    cudaGetSymbolAddress((void**)&Kh,   g_Kh);
    cudaGetSymbolAddress((void**)&Kl,   g_Kl);
    cudaGetSymbolAddress((void**)&Vh,   g_Vh);
    cudaGetSymbolAddress((void**)&Vl,   g_Vl);

    const int DSM  = 1024 + 2 * 65536;   // 132096
    const int FDSM = 1024 + 3 * 65536;
    cudaFuncSetAttribute(gemm_qkv,     cudaFuncAttributeMaxDynamicSharedMemorySize, DSM);
    cudaFuncSetAttribute(gemm_bf,      cudaFuncAttributeMaxDynamicSharedMemorySize, DSM);
    cudaFuncSetAttribute(flash_kernel, cudaFuncAttributeMaxDynamicSharedMemorySize, FDSM);

    // 0) weight planes
    wcvt_kernel<<<(3 * C * C + 255) / 256, 256>>>(qkv_w, qwh, qwl, 3 * C * C);
    wcvt_kernel<<<(C * C + 255) / 256, 256>>>(proj_w, pwh, pwl, C * C);

    // 1) GroupNorm -> xn planes
    gn_t_kernel<<<B * NG, 256>>>(x, gamma, beta, xnh, xnl);

    // 2) QKV GEMM, epilogue writes Q/K/V consumer layouts directly
    gemm_qkv<<<dim3(12, 8, B), 256, DSM>>>(xnh, xnl, qwh, qwl, qkv_b,
                                           Qh, Ql, Kh, Kl, Vh, Vl);

    // 3) fused attention -> att planes [b][n][c]
    flash_kernel<<<dim3(8, B * NH), 256, FDSM>>>(Qh, Ql, Kh, Kl, Vh, Vl, atth, attl);

    // 4) proj + bias + residual: out[b][c][n]
    gemm_bf<<<dim3(8, 4, B), 256, DSM>>>(
        pwh, pwl, C, 0,
        atth, attl, C, (long long)NSP * C,
        out, NSP, (long long)C * NSP,
        C, proj_b, x, NSP, (long long)C * NSP);
}